// round 12
// baseline (speedup 1.0000x reference)
#include <cuda_runtime.h>
#include <cuda_bf16.h>
#include <cuda_fp16.h>
#include <math.h>
#include <stdint.h>

#define N_NODES 50000
#define N_EDGES 800000
#define HIDDEN  256
#define HEADS   4
#define HEAD_DIM 64
#define LAYERS  3
#define NUM_GRAPHS 64
#define NEG_SLOPE 0.2f
#define SCAN_BLOCKS ((N_NODES + 1023) / 1024)   // 49

// ---------------- scratch (device globals; no allocation allowed) ----------------
__device__ float  g_h   [(long long)N_NODES * HIDDEN];
__device__ float  g_hp  [(long long)N_NODES * HIDDEN];
__device__ __half g_hph [(long long)N_NODES * HIDDEN];   // fp16 copy of g_hp for gathers
__device__ float  g_ss  [N_NODES * HEADS];
__device__ float  g_sd  [N_NODES * HEADS];
__device__ float  g_c   [HEADS * 3];
__device__ float  g_pool[NUM_GRAPHS * HIDDEN];
__device__ float  g_cnt [NUM_GRAPHS];
// CSR scratch
__device__ int    g_deg[N_NODES];
__device__ int    g_off[N_NODES + 1];
__device__ int    g_cur[N_NODES];
__device__ int    g_bsum[SCAN_BLOCKS];
__device__ int    g_csr_src[N_EDGES];
__device__ float4 g_csr_att[N_EDGES];
__device__ float4 g_elog[N_EDGES];                       // per-layer leaky logits (4 heads)

// ---------------- helpers ----------------
__device__ __forceinline__ float elu1(float v) {
    return v > 0.f ? v : expm1f(v);
}

// ---------------- init: pooling accumulators + degree histogram ----------------
__global__ void init_kernel() {
    int i = blockIdx.x * blockDim.x + threadIdx.x;
    if (i < NUM_GRAPHS * HIDDEN) g_pool[i] = 0.f;
    if (i < NUM_GRAPHS) g_cnt[i] = 0.f;
    if (i < N_NODES) g_deg[i] = 0;
}

// ---------------- block LN reduce helper (256 threads) ----------------
__device__ __forceinline__ float block_sum_256(float v, float* ws) {
    int lane = threadIdx.x & 31, wid = threadIdx.x >> 5;
    #pragma unroll
    for (int o = 16; o > 0; o >>= 1) v += __shfl_xor_sync(0xFFFFFFFFu, v, o);
    if (lane == 0) ws[wid] = v;
    __syncthreads();
    float s = ws[0] + ws[1] + ws[2] + ws[3] + ws[4] + ws[5] + ws[6] + ws[7];
    __syncthreads();
    return s;
}

// ---------------- input projection + LN + ELU ----------------
__global__ void input_proj_kernel(const float* __restrict__ x,
                                  const float* __restrict__ Win,
                                  const float* __restrict__ bin,
                                  const float* __restrict__ lg,
                                  const float* __restrict__ lb) {
    int n = blockIdx.x;
    int j = threadIdx.x;
    __shared__ float xs[8];
    __shared__ float ws[8];
    if (j < 8) xs[j] = x[n * 8 + j];
    __syncthreads();
    float y = bin[j];
    #pragma unroll
    for (int k = 0; k < 8; k++) y += xs[k] * Win[k * HIDDEN + j];
    float mu = block_sum_256(y, ws) * (1.f / HIDDEN);
    float d = y - mu;
    float var = block_sum_256(d * d, ws) * (1.f / HIDDEN);
    float v = d * rsqrtf(var + 1e-5f) * lg[j] + lb[j];
    g_h[(long long)n * HIDDEN + j] = elu1(v);
}

// ---------------- CSR build ----------------
__global__ void hist_kernel(const int* __restrict__ ei) {
    int e = blockIdx.x * blockDim.x + threadIdx.x;
    if (e >= N_EDGES) return;
    atomicAdd(&g_deg[ei[N_EDGES + e]], 1);
}

__global__ void scan_reduce_kernel() {
    __shared__ int ws[8];
    int b = blockIdx.x;
    int t = threadIdx.x;             // 256 threads
    int base = b * 1024;
    int s = 0;
    #pragma unroll
    for (int i = 0; i < 4; i++) {
        int idx = base + t + i * 256;
        if (idx < N_NODES) s += g_deg[idx];
    }
    int lane = t & 31, wid = t >> 5;
    #pragma unroll
    for (int o = 16; o > 0; o >>= 1) s += __shfl_xor_sync(0xFFFFFFFFu, s, o);
    if (lane == 0) ws[wid] = s;
    __syncthreads();
    if (t == 0) g_bsum[b] = ws[0] + ws[1] + ws[2] + ws[3] + ws[4] + ws[5] + ws[6] + ws[7];
}

__global__ void scan_final_kernel() {
    __shared__ int wtot[32];
    __shared__ int bex[SCAN_BLOCKS];
    int b = blockIdx.x;
    int t = threadIdx.x;             // 1024 threads
    int lane = t & 31, wid = t >> 5;

    if (wid == 0) {
        int v = (lane < SCAN_BLOCKS) ? g_bsum[lane] : 0;
        int incl = v;
        #pragma unroll
        for (int o = 1; o < 32; o <<= 1) {
            int y = __shfl_up_sync(0xFFFFFFFFu, incl, o);
            if (lane >= o) incl += y;
        }
        if (lane < SCAN_BLOCKS) bex[lane] = incl - v;
        int tot = __shfl_sync(0xFFFFFFFFu, incl, 31);
        int v2 = (lane + 32 < SCAN_BLOCKS) ? g_bsum[lane + 32] : 0;
        int incl2 = v2;
        #pragma unroll
        for (int o = 1; o < 32; o <<= 1) {
            int y = __shfl_up_sync(0xFFFFFFFFu, incl2, o);
            if (lane >= o) incl2 += y;
        }
        if (lane + 32 < SCAN_BLOCKS) bex[lane + 32] = tot + incl2 - v2;
    }

    int i = b * 1024 + t;
    int v = (i < N_NODES) ? g_deg[i] : 0;
    int incl = v;
    #pragma unroll
    for (int o = 1; o < 32; o <<= 1) {
        int y = __shfl_up_sync(0xFFFFFFFFu, incl, o);
        if (lane >= o) incl += y;
    }
    if (lane == 31) wtot[wid] = incl;
    __syncthreads();
    if (wid == 0) {
        int w = wtot[lane];
        #pragma unroll
        for (int o = 1; o < 32; o <<= 1) {
            int y = __shfl_up_sync(0xFFFFFFFFu, w, o);
            if (lane >= o) w += y;
        }
        wtot[lane] = w;
    }
    __syncthreads();
    int ex = incl - v + (wid > 0 ? wtot[wid - 1] : 0) + bex[b];
    if (i < N_NODES) {
        g_off[i] = ex;
        g_cur[i] = ex;
    }
    if (b == 0 && t == 0) g_off[N_NODES] = N_EDGES;
}

__global__ void scatter_kernel(const int* __restrict__ ei,
                               const float* __restrict__ ea) {
    int e = blockIdx.x * blockDim.x + threadIdx.x;
    if (e >= N_EDGES) return;
    int s = ei[e];
    int d = ei[N_EDGES + e];
    int pos = atomicAdd(&g_cur[d], 1);
    g_csr_src[pos] = s;
    g_csr_att[pos] = make_float4(ea[e * 3 + 0], ea[e * 3 + 1], ea[e * 3 + 2], 0.f);
}

// ---------------- fp16 mma.sync GEMM: C[M,256] = A[M,256] @ B[256,256] + bias ----------------
// CTA 128x128, 8 warps (2M x 4N), warp tile 64x32 = 4x4 m16n8k16 fragments.
// A smem [m][k] fp16 (stride 40 halves), B smem [n][k] fp16 (stride 40), double-buffered.
#define GBM 128
#define GBN 128
#define GBK 32
#define AH_STRIDE 40
#define BH_STRIDE 40
#define AHSZ (GBM * AH_STRIDE)     // 5120 halves
#define BHSZ (GBN * BH_STRIDE)     // 5120 halves

__global__ void __launch_bounds__(256, 2)
gemm_mma_kernel(const float* __restrict__ A,
                const float* __restrict__ B,
                const float* __restrict__ bias,
                float* __restrict__ C,
                int M) {
    __shared__ __half Ash[2][AHSZ];
    __shared__ __half Bsh[2][BHSZ];

    int tid = threadIdx.x;
    int warp = tid >> 5;
    int lane = tid & 31;
    int wm = warp >> 2;
    int wn = warp & 3;
    int cCol = blockIdx.x;
    int cRow = blockIdx.y;

    int arow_base = tid >> 3;            // 0..31
    int acol4 = (tid & 7) * 4;           // 0..28 (k group)
    int bk = tid >> 5;                   // 0..7 (k base)
    int bn4 = (tid & 31) * 4;            // 0..124 (n group)
    const float* Bb = B + cCol * GBN;

    float acc[4][4][4];
    #pragma unroll
    for (int i = 0; i < 4; i++)
        #pragma unroll
        for (int j = 0; j < 4; j++)
            #pragma unroll
            for (int r = 0; r < 4; r++) acc[i][j][r] = 0.f;

    int lr = lane >> 2;
    int lc = lane & 3;

    float4 ar[4], br[4];
    // prologue: chunk 0
    #pragma unroll
    for (int i = 0; i < 4; i++) {
        int grow = cRow * GBM + arow_base + i * 32;
        ar[i] = (grow < M) ? *(const float4*)&A[(long long)grow * 256 + acol4]
                           : make_float4(0.f, 0.f, 0.f, 0.f);
        br[i] = *(const float4*)&Bb[(long long)(bk + i * 8) * 256 + bn4];
    }
    #pragma unroll
    for (int i = 0; i < 4; i++) {
        __half2 ha = __floats2half2_rn(ar[i].x, ar[i].y);
        __half2 hb = __floats2half2_rn(ar[i].z, ar[i].w);
        uint2 pa = make_uint2(*(uint32_t*)&ha, *(uint32_t*)&hb);
        *(uint2*)&Ash[0][(arow_base + i * 32) * AH_STRIDE + acol4] = pa;
        int k = bk + i * 8;
        Bsh[0][(bn4 + 0) * BH_STRIDE + k] = __float2half_rn(br[i].x);
        Bsh[0][(bn4 + 1) * BH_STRIDE + k] = __float2half_rn(br[i].y);
        Bsh[0][(bn4 + 2) * BH_STRIDE + k] = __float2half_rn(br[i].z);
        Bsh[0][(bn4 + 3) * BH_STRIDE + k] = __float2half_rn(br[i].w);
    }
    __syncthreads();

    for (int kc = 0; kc < 256 / GBK; kc++) {
        int st = kc & 1;
        int nst = st ^ 1;
        if (kc < 7) {
            int kb = (kc + 1) * GBK;
            #pragma unroll
            for (int i = 0; i < 4; i++) {
                int grow = cRow * GBM + arow_base + i * 32;
                ar[i] = (grow < M) ? *(const float4*)&A[(long long)grow * 256 + kb + acol4]
                                   : make_float4(0.f, 0.f, 0.f, 0.f);
                br[i] = *(const float4*)&Bb[(long long)(kb + bk + i * 8) * 256 + bn4];
            }
        }

        const __half* Asb = Ash[st];
        const __half* Bsb = Bsh[st];
        #pragma unroll
        for (int ks = 0; ks < 2; ks++) {
            int k0 = ks * 16;
            uint32_t bf[4][2];
            #pragma unroll
            for (int nt = 0; nt < 4; nt++) {
                int nb = wn * 32 + nt * 8 + lr;
                bf[nt][0] = *(const uint32_t*)&Bsb[nb * BH_STRIDE + k0 + 2 * lc];
                bf[nt][1] = *(const uint32_t*)&Bsb[nb * BH_STRIDE + k0 + 2 * lc + 8];
            }
            #pragma unroll
            for (int mt = 0; mt < 4; mt++) {
                int rm = wm * 64 + mt * 16;
                uint32_t a0 = *(const uint32_t*)&Asb[(rm + lr) * AH_STRIDE + k0 + 2 * lc];
                uint32_t a1 = *(const uint32_t*)&Asb[(rm + lr + 8) * AH_STRIDE + k0 + 2 * lc];
                uint32_t a2 = *(const uint32_t*)&Asb[(rm + lr) * AH_STRIDE + k0 + 2 * lc + 8];
                uint32_t a3 = *(const uint32_t*)&Asb[(rm + lr + 8) * AH_STRIDE + k0 + 2 * lc + 8];
                #pragma unroll
                for (int nt = 0; nt < 4; nt++) {
                    asm volatile(
                        "mma.sync.aligned.m16n8k16.row.col.f32.f16.f16.f32 "
                        "{%0,%1,%2,%3}, {%4,%5,%6,%7}, {%8,%9}, {%0,%1,%2,%3};"
                        : "+f"(acc[mt][nt][0]), "+f"(acc[mt][nt][1]),
                          "+f"(acc[mt][nt][2]), "+f"(acc[mt][nt][3])
                        : "r"(a0), "r"(a1), "r"(a2), "r"(a3),
                          "r"(bf[nt][0]), "r"(bf[nt][1]));
                }
            }
        }
        if (kc < 7) {
            #pragma unroll
            for (int i = 0; i < 4; i++) {
                __half2 ha = __floats2half2_rn(ar[i].x, ar[i].y);
                __half2 hb = __floats2half2_rn(ar[i].z, ar[i].w);
                uint2 pa = make_uint2(*(uint32_t*)&ha, *(uint32_t*)&hb);
                *(uint2*)&Ash[nst][(arow_base + i * 32) * AH_STRIDE + acol4] = pa;
                int k = bk + i * 8;
                Bsh[nst][(bn4 + 0) * BH_STRIDE + k] = __float2half_rn(br[i].x);
                Bsh[nst][(bn4 + 1) * BH_STRIDE + k] = __float2half_rn(br[i].y);
                Bsh[nst][(bn4 + 2) * BH_STRIDE + k] = __float2half_rn(br[i].z);
                Bsh[nst][(bn4 + 3) * BH_STRIDE + k] = __float2half_rn(br[i].w);
            }
        }
        __syncthreads();
    }

    // epilogue: f32 C (+bias) and fp16 copy for the gather path
    #pragma unroll
    for (int mt = 0; mt < 4; mt++) {
        int row0 = cRow * GBM + wm * 64 + mt * 16 + lr;
        #pragma unroll
        for (int nt = 0; nt < 4; nt++) {
            int col = cCol * GBN + wn * 32 + nt * 8 + lc * 2;
            float b0 = bias[col], b1 = bias[col + 1];
            if (row0 < M) {
                float2 v0 = make_float2(acc[mt][nt][0] + b0, acc[mt][nt][1] + b1);
                *(float2*)&C[(long long)row0 * 256 + col] = v0;
                *(__half2*)&g_hph[(long long)row0 * 256 + col] = __floats2half2_rn(v0.x, v0.y);
            }
            if (row0 + 8 < M) {
                float2 v1 = make_float2(acc[mt][nt][2] + b0, acc[mt][nt][3] + b1);
                *(float2*)&C[(long long)(row0 + 8) * 256 + col] = v1;
                *(__half2*)&g_hph[(long long)(row0 + 8) * 256 + col] = __floats2half2_rn(v1.x, v1.y);
            }
        }
    }
}

// ---------------- node attention scores (fp16 input; + per-layer c precompute) ----------------
__global__ void node_score_kernel(const float* __restrict__ as_,
                                  const float* __restrict__ ad_,
                                  const float* __restrict__ We,
                                  const float* __restrict__ ae) {
    if (blockIdx.x == 0 && threadIdx.x < HEADS * 3) {
        int i = threadIdx.x;
        int hh = i / 3, k = i % 3;
        float s = 0.f;
        for (int d = 0; d < HEAD_DIM; d++)
            s += We[k * HIDDEN + hh * HEAD_DIM + d] * ae[hh * HEAD_DIM + d];
        g_c[i] = s;
    }
    int gw = (blockIdx.x * blockDim.x + threadIdx.x) >> 5;
    int lane = threadIdx.x & 31;
    if (gw >= N_NODES * HEADS) return;
    int n = gw >> 2, hh = gw & 3;
    const __half* row = g_hph + (long long)n * HIDDEN + hh * HEAD_DIM;
    float v0 = __half2float(row[lane]), v1 = __half2float(row[lane + 32]);
    float s = v0 * as_[hh * HEAD_DIM + lane] + v1 * as_[hh * HEAD_DIM + lane + 32];
    float t = v0 * ad_[hh * HEAD_DIM + lane] + v1 * ad_[hh * HEAD_DIM + lane + 32];
    #pragma unroll
    for (int o = 16; o > 0; o >>= 1) {
        s += __shfl_xor_sync(0xFFFFFFFFu, s, o);
        t += __shfl_xor_sync(0xFFFFFFFFu, t, o);
    }
    if (lane == 0) {
        g_ss[gw] = s;
        g_sd[gw] = t;
    }
}

// ---------------- fused GAT layer (two-pass): logits+max then exp+agg ----------------
__global__ void gat_fused_kernel() {
    int gw = (blockIdx.x * blockDim.x + threadIdx.x) >> 5;
    int lane = threadIdx.x & 31;
    if (gw >= N_NODES) return;
    int n = gw;
    int r0 = g_off[n], r1 = g_off[n + 1];
    int h = lane >> 3;
    long long hb = (long long)n * HIDDEN + lane * 8;
    float4 hv0 = *(const float4*)&g_h[hb];
    float4 hv1 = *(const float4*)&g_h[hb + 4];

    if (r0 == r1) {
        hv0.x = elu1(hv0.x); hv0.y = elu1(hv0.y); hv0.z = elu1(hv0.z); hv0.w = elu1(hv0.w);
        hv1.x = elu1(hv1.x); hv1.y = elu1(hv1.y); hv1.z = elu1(hv1.z); hv1.w = elu1(hv1.w);
        *(float4*)&g_h[hb] = hv0;
        *(float4*)&g_h[hb + 4] = hv1;
        return;
    }

    float sd0 = g_sd[n * 4 + 0], sd1 = g_sd[n * 4 + 1];
    float sd2 = g_sd[n * 4 + 2], sd3 = g_sd[n * 4 + 3];
    float c00 = g_c[0], c01 = g_c[1],  c02 = g_c[2];
    float c10 = g_c[3], c11 = g_c[4],  c12 = g_c[5];
    float c20 = g_c[6], c21 = g_c[7],  c22 = g_c[8];
    float c30 = g_c[9], c31 = g_c[10], c32 = g_c[11];

    // pass A: logits + per-head max; store leaky logits for pass B
    float m0 = -INFINITY, m1 = -INFINITY, m2 = -INFINITY, m3 = -INFINITY;
    for (int i = r0 + lane; i < r1; i += 32) {
        int s = g_csr_src[i];
        float4 at = g_csr_att[i];
        float l0 = g_ss[s * 4 + 0] + sd0 + at.x * c00 + at.y * c01 + at.z * c02;
        float l1 = g_ss[s * 4 + 1] + sd1 + at.x * c10 + at.y * c11 + at.z * c12;
        float l2 = g_ss[s * 4 + 2] + sd2 + at.x * c20 + at.y * c21 + at.z * c22;
        float l3 = g_ss[s * 4 + 3] + sd3 + at.x * c30 + at.y * c31 + at.z * c32;
        l0 = l0 > 0.f ? l0 : NEG_SLOPE * l0;
        l1 = l1 > 0.f ? l1 : NEG_SLOPE * l1;
        l2 = l2 > 0.f ? l2 : NEG_SLOPE * l2;
        l3 = l3 > 0.f ? l3 : NEG_SLOPE * l3;
        g_elog[i] = make_float4(l0, l1, l2, l3);
        m0 = fmaxf(m0, l0); m1 = fmaxf(m1, l1);
        m2 = fmaxf(m2, l2); m3 = fmaxf(m3, l3);
    }
    #pragma unroll
    for (int o = 16; o > 0; o >>= 1) {
        m0 = fmaxf(m0, __shfl_xor_sync(0xFFFFFFFFu, m0, o));
        m1 = fmaxf(m1, __shfl_xor_sync(0xFFFFFFFFu, m1, o));
        m2 = fmaxf(m2, __shfl_xor_sync(0xFFFFFFFFu, m2, o));
        m3 = fmaxf(m3, __shfl_xor_sync(0xFFFFFFFFu, m3, o));
    }
    float mh = h == 0 ? m0 : (h == 1 ? m1 : (h == 2 ? m2 : m3));
    __syncwarp();   // make lane-written g_elog visible warp-wide

    // pass B: denom + weighted fp16-row aggregation
    const float* elog = (const float*)g_elog;
    float4 a0 = make_float4(0.f, 0.f, 0.f, 0.f);
    float4 a1 = make_float4(0.f, 0.f, 0.f, 0.f);
    float den = 0.f;
    for (int i = r0; i < r1; i++) {
        int s = g_csr_src[i];
        float w = expf(elog[(long long)i * 4 + h] - mh);
        den += w;
        uint4 u = *(const uint4*)&g_hph[(long long)s * HIDDEN + lane * 8];
        float2 f0 = __half22float2(*(__half2*)&u.x);
        float2 f1 = __half22float2(*(__half2*)&u.y);
        float2 f2 = __half22float2(*(__half2*)&u.z);
        float2 f3 = __half22float2(*(__half2*)&u.w);
        a0.x += w * f0.x; a0.y += w * f0.y; a0.z += w * f1.x; a0.w += w * f1.y;
        a1.x += w * f2.x; a1.y += w * f2.y; a1.z += w * f3.x; a1.w += w * f3.y;
    }
    float inv = 1.f / fmaxf(den, 1e-16f);
    hv0.x = elu1(a0.x * inv + hv0.x); hv0.y = elu1(a0.y * inv + hv0.y);
    hv0.z = elu1(a0.z * inv + hv0.z); hv0.w = elu1(a0.w * inv + hv0.w);
    hv1.x = elu1(a1.x * inv + hv1.x); hv1.y = elu1(a1.y * inv + hv1.y);
    hv1.z = elu1(a1.z * inv + hv1.z); hv1.w = elu1(a1.w * inv + hv1.w);
    *(float4*)&g_h[hb] = hv0;
    *(float4*)&g_h[hb + 4] = hv1;
}

// ---------------- output LN + ELU + write node_emb + pool ----------------
__global__ void ln_out_kernel(const float* __restrict__ lg,
                              const float* __restrict__ lb,
                              const int* __restrict__ batch,
                              float* __restrict__ node_out) {
    int n = blockIdx.x;
    int j = threadIdx.x;
    __shared__ float ws[8];
    float y = g_hp[(long long)n * HIDDEN + j];
    float mu = block_sum_256(y, ws) * (1.f / HIDDEN);
    float d = y - mu;
    float var = block_sum_256(d * d, ws) * (1.f / HIDDEN);
    float v = elu1(d * rsqrtf(var + 1e-5f) * lg[j] + lb[j]);
    node_out[(long long)n * HIDDEN + j] = v;
    int b = batch[n];
    atomicAdd(&g_pool[b * HIDDEN + j], v);
    if (j == 0) atomicAdd(&g_cnt[b], 1.0f);
}

// ---------------- graph mean pool output ----------------
__global__ void graph_out_kernel(float* __restrict__ out) {
    int i = blockIdx.x * blockDim.x + threadIdx.x;
    if (i < NUM_GRAPHS * HIDDEN) out[i] = g_pool[i] / fmaxf(g_cnt[i >> 8], 1.0f);
}

// ---------------- launch ----------------
extern "C" void kernel_launch(void* const* d_in, const int* in_sizes, int n_in,
                              void* d_out, int out_size) {
    const float* x          = (const float*)d_in[0];
    const int*   edge_index = (const int*)d_in[1];
    const float* edge_attr  = (const float*)d_in[2];
    const int*   batch      = (const int*)d_in[3];
    const float* W_in       = (const float*)d_in[4];
    const float* b_in       = (const float*)d_in[5];
    const float* ln_in_g    = (const float*)d_in[6];
    const float* ln_in_b    = (const float*)d_in[7];
    const float* W_gat      = (const float*)d_in[8];
    const float* b_gat      = (const float*)d_in[9];
    const float* W_e        = (const float*)d_in[10];
    const float* a_src      = (const float*)d_in[11];
    const float* a_dst      = (const float*)d_in[12];
    const float* a_edge     = (const float*)d_in[13];
    const float* W_out      = (const float*)d_in[14];
    const float* b_out      = (const float*)d_in[15];
    const float* ln_out_g   = (const float*)d_in[16];
    const float* ln_out_b   = (const float*)d_in[17];

    float* out = (float*)d_out;

    float *hp_, *h_;
    cudaGetSymbolAddress((void**)&h_, g_h);
    cudaGetSymbolAddress((void**)&hp_, g_hp);

    long long node_off = (long long)out_size - (long long)N_NODES * HIDDEN;
    float* node_out = (node_off >= 0) ? out + node_off : hp_;

    init_kernel<<<(N_NODES + 255) / 256, 256>>>();
    input_proj_kernel<<<N_NODES, HIDDEN>>>(x, W_in, b_in, ln_in_g, ln_in_b);
    hist_kernel<<<(N_EDGES + 255) / 256, 256>>>(edge_index);
    scan_reduce_kernel<<<SCAN_BLOCKS, 256>>>();
    scan_final_kernel<<<SCAN_BLOCKS, 1024>>>();
    scatter_kernel<<<(N_EDGES + 255) / 256, 256>>>(edge_index, edge_attr);

    dim3 gemm_grid(2, (N_NODES + GBM - 1) / GBM);
    int score_blocks = (N_NODES * HEADS * 32 + 255) / 256;
    int gat_blocks = (N_NODES * 32 + 255) / 256;

    for (int l = 0; l < LAYERS; l++) {
        const float* Wl  = W_gat + (long long)l * HIDDEN * HIDDEN;
        const float* bl  = b_gat + l * HIDDEN;
        const float* Wel = W_e + l * 3 * HIDDEN;
        const float* asl = a_src + l * HEADS * HEAD_DIM;
        const float* adl = a_dst + l * HEADS * HEAD_DIM;
        const float* ael = a_edge + l * HEADS * HEAD_DIM;

        gemm_mma_kernel<<<gemm_grid, 256>>>(h_, Wl, bl, hp_, N_NODES);
        node_score_kernel<<<score_blocks, 256>>>(asl, adl, Wel, ael);
        gat_fused_kernel<<<gat_blocks, 256>>>();
    }

    gemm_mma_kernel<<<gemm_grid, 256>>>(h_, W_out, b_out, hp_, N_NODES);
    ln_out_kernel<<<N_NODES, HIDDEN>>>(ln_out_g, ln_out_b, batch, node_out);
    graph_out_kernel<<<(NUM_GRAPHS * HIDDEN + 255) / 256, 256>>>(out);
}

// round 13
// speedup vs baseline: 1.1817x; 1.1817x over previous
#include <cuda_runtime.h>
#include <cuda_bf16.h>
#include <cuda_fp16.h>
#include <math.h>
#include <stdint.h>

#define N_NODES 50000
#define N_EDGES 800000
#define HIDDEN  256
#define HEADS   4
#define HEAD_DIM 64
#define LAYERS  3
#define NUM_GRAPHS 64
#define NEG_SLOPE 0.2f
#define SCAN_BLOCKS ((N_NODES + 1023) / 1024)   // 49

// ---------------- scratch (device globals; no allocation allowed) ----------------
__device__ float  g_h   [(long long)N_NODES * HIDDEN];
__device__ float  g_hp  [(long long)N_NODES * HIDDEN];
__device__ __half g_hph [(long long)N_NODES * HIDDEN];   // fp16 copy of g_hp for gathers
__device__ float  g_ss  [N_NODES * HEADS];
__device__ float  g_sd  [N_NODES * HEADS];
__device__ float  g_c   [HEADS * 3];
__device__ float  g_pool[NUM_GRAPHS * HIDDEN];
__device__ float  g_cnt [NUM_GRAPHS];
// CSR scratch
__device__ int    g_deg[N_NODES];
__device__ int    g_off[N_NODES + 1];
__device__ int    g_cur[N_NODES];
__device__ int    g_bsum[SCAN_BLOCKS];
__device__ int    g_csr_src[N_EDGES];
__device__ float4 g_csr_att[N_EDGES];
__device__ float4 g_elog[N_EDGES];                       // per-layer leaky logits (4 heads)

// ---------------- helpers ----------------
__device__ __forceinline__ float elu1(float v) {
    return v > 0.f ? v : expm1f(v);
}

__device__ __forceinline__ uint32_t f2tf32(float x) {
    uint32_t u;
    asm("cvt.rna.tf32.f32 %0, %1;" : "=r"(u) : "f"(x));
    return u;
}

// ---------------- init: pooling accumulators + degree histogram ----------------
__global__ void init_kernel() {
    int i = blockIdx.x * blockDim.x + threadIdx.x;
    if (i < NUM_GRAPHS * HIDDEN) g_pool[i] = 0.f;
    if (i < NUM_GRAPHS) g_cnt[i] = 0.f;
    if (i < N_NODES) g_deg[i] = 0;
}

// ---------------- block LN reduce helper (256 threads) ----------------
__device__ __forceinline__ float block_sum_256(float v, float* ws) {
    int lane = threadIdx.x & 31, wid = threadIdx.x >> 5;
    #pragma unroll
    for (int o = 16; o > 0; o >>= 1) v += __shfl_xor_sync(0xFFFFFFFFu, v, o);
    if (lane == 0) ws[wid] = v;
    __syncthreads();
    float s = ws[0] + ws[1] + ws[2] + ws[3] + ws[4] + ws[5] + ws[6] + ws[7];
    __syncthreads();
    return s;
}

// ---------------- input projection + LN + ELU ----------------
__global__ void input_proj_kernel(const float* __restrict__ x,
                                  const float* __restrict__ Win,
                                  const float* __restrict__ bin,
                                  const float* __restrict__ lg,
                                  const float* __restrict__ lb) {
    int n = blockIdx.x;
    int j = threadIdx.x;
    __shared__ float xs[8];
    __shared__ float ws[8];
    if (j < 8) xs[j] = x[n * 8 + j];
    __syncthreads();
    float y = bin[j];
    #pragma unroll
    for (int k = 0; k < 8; k++) y += xs[k] * Win[k * HIDDEN + j];
    float mu = block_sum_256(y, ws) * (1.f / HIDDEN);
    float d = y - mu;
    float var = block_sum_256(d * d, ws) * (1.f / HIDDEN);
    float v = d * rsqrtf(var + 1e-5f) * lg[j] + lb[j];
    g_h[(long long)n * HIDDEN + j] = elu1(v);
}

// ---------------- CSR build ----------------
__global__ void hist_kernel(const int* __restrict__ ei) {
    int e = blockIdx.x * blockDim.x + threadIdx.x;
    if (e >= N_EDGES) return;
    atomicAdd(&g_deg[ei[N_EDGES + e]], 1);
}

__global__ void scan_reduce_kernel() {
    __shared__ int ws[8];
    int b = blockIdx.x;
    int t = threadIdx.x;             // 256 threads
    int base = b * 1024;
    int s = 0;
    #pragma unroll
    for (int i = 0; i < 4; i++) {
        int idx = base + t + i * 256;
        if (idx < N_NODES) s += g_deg[idx];
    }
    int lane = t & 31, wid = t >> 5;
    #pragma unroll
    for (int o = 16; o > 0; o >>= 1) s += __shfl_xor_sync(0xFFFFFFFFu, s, o);
    if (lane == 0) ws[wid] = s;
    __syncthreads();
    if (t == 0) g_bsum[b] = ws[0] + ws[1] + ws[2] + ws[3] + ws[4] + ws[5] + ws[6] + ws[7];
}

__global__ void scan_final_kernel() {
    __shared__ int wtot[32];
    __shared__ int bex[SCAN_BLOCKS];
    int b = blockIdx.x;
    int t = threadIdx.x;             // 1024 threads
    int lane = t & 31, wid = t >> 5;

    if (wid == 0) {
        int v = (lane < SCAN_BLOCKS) ? g_bsum[lane] : 0;
        int incl = v;
        #pragma unroll
        for (int o = 1; o < 32; o <<= 1) {
            int y = __shfl_up_sync(0xFFFFFFFFu, incl, o);
            if (lane >= o) incl += y;
        }
        if (lane < SCAN_BLOCKS) bex[lane] = incl - v;
        int tot = __shfl_sync(0xFFFFFFFFu, incl, 31);
        int v2 = (lane + 32 < SCAN_BLOCKS) ? g_bsum[lane + 32] : 0;
        int incl2 = v2;
        #pragma unroll
        for (int o = 1; o < 32; o <<= 1) {
            int y = __shfl_up_sync(0xFFFFFFFFu, incl2, o);
            if (lane >= o) incl2 += y;
        }
        if (lane + 32 < SCAN_BLOCKS) bex[lane + 32] = tot + incl2 - v2;
    }

    int i = b * 1024 + t;
    int v = (i < N_NODES) ? g_deg[i] : 0;
    int incl = v;
    #pragma unroll
    for (int o = 1; o < 32; o <<= 1) {
        int y = __shfl_up_sync(0xFFFFFFFFu, incl, o);
        if (lane >= o) incl += y;
    }
    if (lane == 31) wtot[wid] = incl;
    __syncthreads();
    if (wid == 0) {
        int w = wtot[lane];
        #pragma unroll
        for (int o = 1; o < 32; o <<= 1) {
            int y = __shfl_up_sync(0xFFFFFFFFu, w, o);
            if (lane >= o) w += y;
        }
        wtot[lane] = w;
    }
    __syncthreads();
    int ex = incl - v + (wid > 0 ? wtot[wid - 1] : 0) + bex[b];
    if (i < N_NODES) {
        g_off[i] = ex;
        g_cur[i] = ex;
    }
    if (b == 0 && t == 0) g_off[N_NODES] = N_EDGES;
}

__global__ void scatter_kernel(const int* __restrict__ ei,
                               const float* __restrict__ ea) {
    int e = blockIdx.x * blockDim.x + threadIdx.x;
    if (e >= N_EDGES) return;
    int s = ei[e];
    int d = ei[N_EDGES + e];
    int pos = atomicAdd(&g_cur[d], 1);
    g_csr_src[pos] = s;
    g_csr_att[pos] = make_float4(ea[e * 3 + 0], ea[e * 3 + 1], ea[e * 3 + 2], 0.f);
}

// ---------------- mma.sync tf32 GEMM: C[M,256] = A[M,256] @ B[256,256] + bias ----------------
// write_mode 0: fp16 copy only (layer GEMMs; f32 C unused)
// write_mode 1: f32 C only (final GEMM; fp16 copy unused)
#define GBM 128
#define GBN 128
#define GBK 32
#define A_STRIDE 36
#define B_STRIDE 136
#define ASZ (GBM * A_STRIDE)
#define BSZ (GBK * B_STRIDE)
#define GEMM_DSMEM (2 * (ASZ + BSZ) * 4)

__global__ void __launch_bounds__(256, 2)
gemm_mma_kernel(const float* __restrict__ A,
                const float* __restrict__ B,
                const float* __restrict__ bias,
                float* __restrict__ C,
                int M, int write_mode) {
    extern __shared__ uint32_t sm[];
    uint32_t* As = sm;               // [2][ASZ]
    uint32_t* Bs = sm + 2 * ASZ;     // [2][BSZ]

    int tid = threadIdx.x;
    int warp = tid >> 5;
    int lane = tid & 31;
    int wm = warp >> 2;
    int wn = warp & 3;
    int cCol = blockIdx.x;
    int cRow = blockIdx.y;

    int arow_base = tid >> 3;            // 0..31
    int acol4 = (tid & 7) * 4;           // 0..28
    int bk = tid >> 5;                   // 0..7
    int bn4 = (tid & 31) * 4;            // 0..124
    const float* Bb = B + cCol * GBN;

    float acc[4][4][4];
    #pragma unroll
    for (int i = 0; i < 4; i++)
        #pragma unroll
        for (int j = 0; j < 4; j++)
            #pragma unroll
            for (int r = 0; r < 4; r++) acc[i][j][r] = 0.f;

    int lr = lane >> 2;
    int lc = lane & 3;

    float4 ar[4], br[4];
    #pragma unroll
    for (int i = 0; i < 4; i++) {
        int grow = cRow * GBM + arow_base + i * 32;
        ar[i] = (grow < M) ? *(const float4*)&A[(long long)grow * 256 + acol4]
                           : make_float4(0.f, 0.f, 0.f, 0.f);
        br[i] = *(const float4*)&Bb[(long long)(bk + i * 8) * 256 + bn4];
    }
    #pragma unroll
    for (int i = 0; i < 4; i++) {
        *(uint4*)&As[(arow_base + i * 32) * A_STRIDE + acol4] =
            make_uint4(f2tf32(ar[i].x), f2tf32(ar[i].y), f2tf32(ar[i].z), f2tf32(ar[i].w));
        *(uint4*)&Bs[(bk + i * 8) * B_STRIDE + bn4] =
            make_uint4(f2tf32(br[i].x), f2tf32(br[i].y), f2tf32(br[i].z), f2tf32(br[i].w));
    }
    __syncthreads();

    for (int kc = 0; kc < 256 / GBK; kc++) {
        int st = kc & 1;
        int nst = st ^ 1;
        if (kc < 7) {
            int kb = (kc + 1) * GBK;
            #pragma unroll
            for (int i = 0; i < 4; i++) {
                int grow = cRow * GBM + arow_base + i * 32;
                ar[i] = (grow < M) ? *(const float4*)&A[(long long)grow * 256 + kb + acol4]
                                   : make_float4(0.f, 0.f, 0.f, 0.f);
                br[i] = *(const float4*)&Bb[(long long)(kb + bk + i * 8) * 256 + bn4];
            }
        }

        const uint32_t* Asb = As + st * ASZ;
        const uint32_t* Bsb = Bs + st * BSZ;
        #pragma unroll
        for (int ks = 0; ks < GBK / 8; ks++) {
            int k0 = ks * 8;
            uint32_t bf[4][2];
            #pragma unroll
            for (int nt = 0; nt < 4; nt++) {
                int nb = wn * 32 + nt * 8 + lr;
                bf[nt][0] = Bsb[(k0 + lc) * B_STRIDE + nb];
                bf[nt][1] = Bsb[(k0 + lc + 4) * B_STRIDE + nb];
            }
            #pragma unroll
            for (int mt = 0; mt < 4; mt++) {
                int rm = wm * 64 + mt * 16;
                uint32_t a0 = Asb[(rm + lr) * A_STRIDE + k0 + lc];
                uint32_t a1 = Asb[(rm + lr + 8) * A_STRIDE + k0 + lc];
                uint32_t a2 = Asb[(rm + lr) * A_STRIDE + k0 + lc + 4];
                uint32_t a3 = Asb[(rm + lr + 8) * A_STRIDE + k0 + lc + 4];
                #pragma unroll
                for (int nt = 0; nt < 4; nt++) {
                    asm volatile(
                        "mma.sync.aligned.m16n8k8.row.col.f32.tf32.tf32.f32 "
                        "{%0,%1,%2,%3}, {%4,%5,%6,%7}, {%8,%9}, {%0,%1,%2,%3};"
                        : "+f"(acc[mt][nt][0]), "+f"(acc[mt][nt][1]),
                          "+f"(acc[mt][nt][2]), "+f"(acc[mt][nt][3])
                        : "r"(a0), "r"(a1), "r"(a2), "r"(a3),
                          "r"(bf[nt][0]), "r"(bf[nt][1]));
                }
            }
        }
        if (kc < 7) {
            uint32_t* Asn = As + nst * ASZ;
            uint32_t* Bsn = Bs + nst * BSZ;
            #pragma unroll
            for (int i = 0; i < 4; i++) {
                *(uint4*)&Asn[(arow_base + i * 32) * A_STRIDE + acol4] =
                    make_uint4(f2tf32(ar[i].x), f2tf32(ar[i].y), f2tf32(ar[i].z), f2tf32(ar[i].w));
                *(uint4*)&Bsn[(bk + i * 8) * B_STRIDE + bn4] =
                    make_uint4(f2tf32(br[i].x), f2tf32(br[i].y), f2tf32(br[i].z), f2tf32(br[i].w));
            }
        }
        __syncthreads();
    }

    // epilogue (+bias): layers -> fp16 copy only; final -> f32 only
    #pragma unroll
    for (int mt = 0; mt < 4; mt++) {
        int row0 = cRow * GBM + wm * 64 + mt * 16 + lr;
        #pragma unroll
        for (int nt = 0; nt < 4; nt++) {
            int col = cCol * GBN + wn * 32 + nt * 8 + lc * 2;
            float b0 = bias[col], b1 = bias[col + 1];
            float2 v0 = make_float2(acc[mt][nt][0] + b0, acc[mt][nt][1] + b1);
            float2 v1 = make_float2(acc[mt][nt][2] + b0, acc[mt][nt][3] + b1);
            if (write_mode == 0) {
                if (row0 < M)
                    *(__half2*)&g_hph[(long long)row0 * 256 + col] = __floats2half2_rn(v0.x, v0.y);
                if (row0 + 8 < M)
                    *(__half2*)&g_hph[(long long)(row0 + 8) * 256 + col] = __floats2half2_rn(v1.x, v1.y);
            } else {
                if (row0 < M)
                    *(float2*)&C[(long long)row0 * 256 + col] = v0;
                if (row0 + 8 < M)
                    *(float2*)&C[(long long)(row0 + 8) * 256 + col] = v1;
            }
        }
    }
}

// ---------------- node attention scores (fp16 input; + per-layer c precompute) ----------------
__global__ void node_score_kernel(const float* __restrict__ as_,
                                  const float* __restrict__ ad_,
                                  const float* __restrict__ We,
                                  const float* __restrict__ ae) {
    if (blockIdx.x == 0 && threadIdx.x < HEADS * 3) {
        int i = threadIdx.x;
        int hh = i / 3, k = i % 3;
        float s = 0.f;
        for (int d = 0; d < HEAD_DIM; d++)
            s += We[k * HIDDEN + hh * HEAD_DIM + d] * ae[hh * HEAD_DIM + d];
        g_c[i] = s;
    }
    int gw = (blockIdx.x * blockDim.x + threadIdx.x) >> 5;
    int lane = threadIdx.x & 31;
    if (gw >= N_NODES * HEADS) return;
    int n = gw >> 2, hh = gw & 3;
    const __half* row = g_hph + (long long)n * HIDDEN + hh * HEAD_DIM;
    float v0 = __half2float(row[lane]), v1 = __half2float(row[lane + 32]);
    float s = v0 * as_[hh * HEAD_DIM + lane] + v1 * as_[hh * HEAD_DIM + lane + 32];
    float t = v0 * ad_[hh * HEAD_DIM + lane] + v1 * ad_[hh * HEAD_DIM + lane + 32];
    #pragma unroll
    for (int o = 16; o > 0; o >>= 1) {
        s += __shfl_xor_sync(0xFFFFFFFFu, s, o);
        t += __shfl_xor_sync(0xFFFFFFFFu, t, o);
    }
    if (lane == 0) {
        g_ss[gw] = s;
        g_sd[gw] = t;
    }
}

// ---------------- fused GAT layer (two-pass): logits+max then exp+agg ----------------
__global__ void gat_fused_kernel() {
    int gw = (blockIdx.x * blockDim.x + threadIdx.x) >> 5;
    int lane = threadIdx.x & 31;
    if (gw >= N_NODES) return;
    int n = gw;
    int r0 = g_off[n], r1 = g_off[n + 1];
    int h = lane >> 3;
    long long hb = (long long)n * HIDDEN + lane * 8;
    float4 hv0 = *(const float4*)&g_h[hb];
    float4 hv1 = *(const float4*)&g_h[hb + 4];

    if (r0 == r1) {
        hv0.x = elu1(hv0.x); hv0.y = elu1(hv0.y); hv0.z = elu1(hv0.z); hv0.w = elu1(hv0.w);
        hv1.x = elu1(hv1.x); hv1.y = elu1(hv1.y); hv1.z = elu1(hv1.z); hv1.w = elu1(hv1.w);
        *(float4*)&g_h[hb] = hv0;
        *(float4*)&g_h[hb + 4] = hv1;
        return;
    }

    float sd0 = g_sd[n * 4 + 0], sd1 = g_sd[n * 4 + 1];
    float sd2 = g_sd[n * 4 + 2], sd3 = g_sd[n * 4 + 3];
    float c00 = g_c[0], c01 = g_c[1],  c02 = g_c[2];
    float c10 = g_c[3], c11 = g_c[4],  c12 = g_c[5];
    float c20 = g_c[6], c21 = g_c[7],  c22 = g_c[8];
    float c30 = g_c[9], c31 = g_c[10], c32 = g_c[11];

    // pass A: logits + per-head max; store leaky logits for pass B
    float m0 = -INFINITY, m1 = -INFINITY, m2 = -INFINITY, m3 = -INFINITY;
    for (int i = r0 + lane; i < r1; i += 32) {
        int s = g_csr_src[i];
        float4 at = g_csr_att[i];
        float l0 = g_ss[s * 4 + 0] + sd0 + at.x * c00 + at.y * c01 + at.z * c02;
        float l1 = g_ss[s * 4 + 1] + sd1 + at.x * c10 + at.y * c11 + at.z * c12;
        float l2 = g_ss[s * 4 + 2] + sd2 + at.x * c20 + at.y * c21 + at.z * c22;
        float l3 = g_ss[s * 4 + 3] + sd3 + at.x * c30 + at.y * c31 + at.z * c32;
        l0 = l0 > 0.f ? l0 : NEG_SLOPE * l0;
        l1 = l1 > 0.f ? l1 : NEG_SLOPE * l1;
        l2 = l2 > 0.f ? l2 : NEG_SLOPE * l2;
        l3 = l3 > 0.f ? l3 : NEG_SLOPE * l3;
        g_elog[i] = make_float4(l0, l1, l2, l3);
        m0 = fmaxf(m0, l0); m1 = fmaxf(m1, l1);
        m2 = fmaxf(m2, l2); m3 = fmaxf(m3, l3);
    }
    #pragma unroll
    for (int o = 16; o > 0; o >>= 1) {
        m0 = fmaxf(m0, __shfl_xor_sync(0xFFFFFFFFu, m0, o));
        m1 = fmaxf(m1, __shfl_xor_sync(0xFFFFFFFFu, m1, o));
        m2 = fmaxf(m2, __shfl_xor_sync(0xFFFFFFFFu, m2, o));
        m3 = fmaxf(m3, __shfl_xor_sync(0xFFFFFFFFu, m3, o));
    }
    float mh = h == 0 ? m0 : (h == 1 ? m1 : (h == 2 ? m2 : m3));
    __syncwarp();   // make lane-written g_elog visible warp-wide

    // pass B: denom + weighted fp16-row aggregation
    const float* elog = (const float*)g_elog;
    float4 a0 = make_float4(0.f, 0.f, 0.f, 0.f);
    float4 a1 = make_float4(0.f, 0.f, 0.f, 0.f);
    float den = 0.f;
    for (int i = r0; i < r1; i++) {
        int s = g_csr_src[i];
        float w = expf(elog[(long long)i * 4 + h] - mh);
        den += w;
        uint4 u = *(const uint4*)&g_hph[(long long)s * HIDDEN + lane * 8];
        float2 f0 = __half22float2(*(__half2*)&u.x);
        float2 f1 = __half22float2(*(__half2*)&u.y);
        float2 f2 = __half22float2(*(__half2*)&u.z);
        float2 f3 = __half22float2(*(__half2*)&u.w);
        a0.x += w * f0.x; a0.y += w * f0.y; a0.z += w * f1.x; a0.w += w * f1.y;
        a1.x += w * f2.x; a1.y += w * f2.y; a1.z += w * f3.x; a1.w += w * f3.y;
    }
    float inv = 1.f / fmaxf(den, 1e-16f);
    hv0.x = elu1(a0.x * inv + hv0.x); hv0.y = elu1(a0.y * inv + hv0.y);
    hv0.z = elu1(a0.z * inv + hv0.z); hv0.w = elu1(a0.w * inv + hv0.w);
    hv1.x = elu1(a1.x * inv + hv1.x); hv1.y = elu1(a1.y * inv + hv1.y);
    hv1.z = elu1(a1.z * inv + hv1.z); hv1.w = elu1(a1.w * inv + hv1.w);
    *(float4*)&g_h[hb] = hv0;
    *(float4*)&g_h[hb + 4] = hv1;
}

// ---------------- output LN + ELU + write node_emb + pool ----------------
__global__ void ln_out_kernel(const float* __restrict__ lg,
                              const float* __restrict__ lb,
                              const int* __restrict__ batch,
                              float* __restrict__ node_out) {
    int n = blockIdx.x;
    int j = threadIdx.x;
    __shared__ float ws[8];
    float y = g_hp[(long long)n * HIDDEN + j];
    float mu = block_sum_256(y, ws) * (1.f / HIDDEN);
    float d = y - mu;
    float var = block_sum_256(d * d, ws) * (1.f / HIDDEN);
    float v = elu1(d * rsqrtf(var + 1e-5f) * lg[j] + lb[j]);
    node_out[(long long)n * HIDDEN + j] = v;
    int b = batch[n];
    atomicAdd(&g_pool[b * HIDDEN + j], v);
    if (j == 0) atomicAdd(&g_cnt[b], 1.0f);
}

// ---------------- graph mean pool output ----------------
__global__ void graph_out_kernel(float* __restrict__ out) {
    int i = blockIdx.x * blockDim.x + threadIdx.x;
    if (i < NUM_GRAPHS * HIDDEN) out[i] = g_pool[i] / fmaxf(g_cnt[i >> 8], 1.0f);
}

// ---------------- launch ----------------
extern "C" void kernel_launch(void* const* d_in, const int* in_sizes, int n_in,
                              void* d_out, int out_size) {
    const float* x          = (const float*)d_in[0];
    const int*   edge_index = (const int*)d_in[1];
    const float* edge_attr  = (const float*)d_in[2];
    const int*   batch      = (const int*)d_in[3];
    const float* W_in       = (const float*)d_in[4];
    const float* b_in       = (const float*)d_in[5];
    const float* ln_in_g    = (const float*)d_in[6];
    const float* ln_in_b    = (const float*)d_in[7];
    const float* W_gat      = (const float*)d_in[8];
    const float* b_gat      = (const float*)d_in[9];
    const float* W_e        = (const float*)d_in[10];
    const float* a_src      = (const float*)d_in[11];
    const float* a_dst      = (const float*)d_in[12];
    const float* a_edge     = (const float*)d_in[13];
    const float* W_out      = (const float*)d_in[14];
    const float* b_out      = (const float*)d_in[15];
    const float* ln_out_g   = (const float*)d_in[16];
    const float* ln_out_b   = (const float*)d_in[17];

    float* out = (float*)d_out;

    float *hp_, *h_;
    cudaGetSymbolAddress((void**)&h_, g_h);
    cudaGetSymbolAddress((void**)&hp_, g_hp);

    long long node_off = (long long)out_size - (long long)N_NODES * HIDDEN;
    float* node_out = (node_off >= 0) ? out + node_off : hp_;

    static int smem_set = 0;
    if (!smem_set) {
        cudaFuncSetAttribute(gemm_mma_kernel, cudaFuncAttributeMaxDynamicSharedMemorySize,
                             GEMM_DSMEM);
        smem_set = 1;
    }

    init_kernel<<<(N_NODES + 255) / 256, 256>>>();
    input_proj_kernel<<<N_NODES, HIDDEN>>>(x, W_in, b_in, ln_in_g, ln_in_b);
    hist_kernel<<<(N_EDGES + 255) / 256, 256>>>(edge_index);
    scan_reduce_kernel<<<SCAN_BLOCKS, 256>>>();
    scan_final_kernel<<<SCAN_BLOCKS, 1024>>>();
    scatter_kernel<<<(N_EDGES + 255) / 256, 256>>>(edge_index, edge_attr);

    dim3 gemm_grid(2, (N_NODES + GBM - 1) / GBM);
    int score_blocks = (N_NODES * HEADS * 32 + 255) / 256;
    int gat_blocks = (N_NODES * 32 + 255) / 256;

    for (int l = 0; l < LAYERS; l++) {
        const float* Wl  = W_gat + (long long)l * HIDDEN * HIDDEN;
        const float* bl  = b_gat + l * HIDDEN;
        const float* Wel = W_e + l * 3 * HIDDEN;
        const float* asl = a_src + l * HEADS * HEAD_DIM;
        const float* adl = a_dst + l * HEADS * HEAD_DIM;
        const float* ael = a_edge + l * HEADS * HEAD_DIM;

        gemm_mma_kernel<<<gemm_grid, 256, GEMM_DSMEM>>>(h_, Wl, bl, hp_, N_NODES, 0);
        node_score_kernel<<<score_blocks, 256>>>(asl, adl, Wel, ael);
        gat_fused_kernel<<<gat_blocks, 256>>>();
    }

    gemm_mma_kernel<<<gemm_grid, 256, GEMM_DSMEM>>>(h_, W_out, b_out, hp_, N_NODES, 1);
    ln_out_kernel<<<N_NODES, HIDDEN>>>(ln_out_g, ln_out_b, batch, node_out);
    graph_out_kernel<<<(NUM_GRAPHS * HIDDEN + 255) / 256, 256>>>(out);
}

// round 14
// speedup vs baseline: 1.2297x; 1.0406x over previous
#include <cuda_runtime.h>
#include <cuda_bf16.h>
#include <cuda_fp16.h>
#include <math.h>
#include <stdint.h>

#define N_NODES 50000
#define N_EDGES 800000
#define HIDDEN  256
#define HEADS   4
#define HEAD_DIM 64
#define LAYERS  3
#define NUM_GRAPHS 64
#define NEG_SLOPE 0.2f
#define SCAN_BLOCKS ((N_NODES + 1023) / 1024)   // 49

// ---------------- scratch (device globals; no allocation allowed) ----------------
__device__ float  g_h   [(long long)N_NODES * HIDDEN];   // tf32-rounded activations
__device__ float  g_hp  [(long long)N_NODES * HIDDEN];
__device__ __half g_hph [(long long)N_NODES * HIDDEN];   // fp16 copy of projections for gathers
__device__ float  g_wtf [4 * HIDDEN * HIDDEN];           // tf32-rounded weights (3 GAT + out)
__device__ float  g_ss  [N_NODES * HEADS];
__device__ float  g_sd  [N_NODES * HEADS];
__device__ float  g_c   [HEADS * 3];
__device__ float  g_pool[NUM_GRAPHS * HIDDEN];
__device__ float  g_cnt [NUM_GRAPHS];
// CSR scratch
__device__ int    g_deg[N_NODES];
__device__ int    g_off[N_NODES + 1];
__device__ int    g_cur[N_NODES];
__device__ int    g_bsum[SCAN_BLOCKS];
__device__ int    g_csr_src[N_EDGES];
__device__ float4 g_csr_att[N_EDGES];
__device__ float4 g_elog[N_EDGES];                       // per-layer leaky logits (4 heads)

// ---------------- helpers ----------------
__device__ __forceinline__ float elu1(float v) {
    return v > 0.f ? v : expm1f(v);
}

__device__ __forceinline__ uint32_t f2tf32(float x) {
    uint32_t u;
    asm("cvt.rna.tf32.f32 %0, %1;" : "=r"(u) : "f"(x));
    return u;
}

__device__ __forceinline__ float rtf(float x) {        // tf32-rounded float
    return __uint_as_float(f2tf32(x));
}

__device__ __forceinline__ void cp16(uint32_t saddr, const void* g) {
    asm volatile("cp.async.cg.shared.global [%0], [%1], 16;" :: "r"(saddr), "l"(g));
}
__device__ __forceinline__ void cp16_pred(uint32_t saddr, const void* g, bool p) {
    int sz = p ? 16 : 0;
    asm volatile("cp.async.cg.shared.global [%0], [%1], 16, %2;" :: "r"(saddr), "l"(g), "r"(sz));
}
#define CP_COMMIT() asm volatile("cp.async.commit_group;" ::: "memory")
#define CP_WAIT0()  asm volatile("cp.async.wait_group 0;" ::: "memory")

// ---------------- weight pre-round (once per launch) ----------------
__global__ void prep_w_kernel(const float* __restrict__ Wg, const float* __restrict__ Wo) {
    int i = blockIdx.x * blockDim.x + threadIdx.x;     // float4 index
    if (i >= 65536) return;
    long long f = (long long)i * 4;
    float4 v = (f < 196608) ? *(const float4*)(Wg + f)
                            : *(const float4*)(Wo + (f - 196608));
    uint4 r = make_uint4(f2tf32(v.x), f2tf32(v.y), f2tf32(v.z), f2tf32(v.w));
    ((uint4*)g_wtf)[i] = r;
}

// ---------------- init: pooling accumulators + degree histogram ----------------
__global__ void init_kernel() {
    int i = blockIdx.x * blockDim.x + threadIdx.x;
    if (i < NUM_GRAPHS * HIDDEN) g_pool[i] = 0.f;
    if (i < NUM_GRAPHS) g_cnt[i] = 0.f;
    if (i < N_NODES) g_deg[i] = 0;
}

// ---------------- block LN reduce helper (256 threads) ----------------
__device__ __forceinline__ float block_sum_256(float v, float* ws) {
    int lane = threadIdx.x & 31, wid = threadIdx.x >> 5;
    #pragma unroll
    for (int o = 16; o > 0; o >>= 1) v += __shfl_xor_sync(0xFFFFFFFFu, v, o);
    if (lane == 0) ws[wid] = v;
    __syncthreads();
    float s = ws[0] + ws[1] + ws[2] + ws[3] + ws[4] + ws[5] + ws[6] + ws[7];
    __syncthreads();
    return s;
}

// ---------------- input projection + LN + ELU (writes tf32-rounded h) ----------------
__global__ void input_proj_kernel(const float* __restrict__ x,
                                  const float* __restrict__ Win,
                                  const float* __restrict__ bin,
                                  const float* __restrict__ lg,
                                  const float* __restrict__ lb) {
    int n = blockIdx.x;
    int j = threadIdx.x;
    __shared__ float xs[8];
    __shared__ float ws[8];
    if (j < 8) xs[j] = x[n * 8 + j];
    __syncthreads();
    float y = bin[j];
    #pragma unroll
    for (int k = 0; k < 8; k++) y += xs[k] * Win[k * HIDDEN + j];
    float mu = block_sum_256(y, ws) * (1.f / HIDDEN);
    float d = y - mu;
    float var = block_sum_256(d * d, ws) * (1.f / HIDDEN);
    float v = d * rsqrtf(var + 1e-5f) * lg[j] + lb[j];
    g_h[(long long)n * HIDDEN + j] = rtf(elu1(v));
}

// ---------------- CSR build ----------------
__global__ void hist_kernel(const int* __restrict__ ei) {
    int e = blockIdx.x * blockDim.x + threadIdx.x;
    if (e >= N_EDGES) return;
    atomicAdd(&g_deg[ei[N_EDGES + e]], 1);
}

__global__ void scan_reduce_kernel() {
    __shared__ int ws[8];
    int b = blockIdx.x;
    int t = threadIdx.x;             // 256 threads
    int base = b * 1024;
    int s = 0;
    #pragma unroll
    for (int i = 0; i < 4; i++) {
        int idx = base + t + i * 256;
        if (idx < N_NODES) s += g_deg[idx];
    }
    int lane = t & 31, wid = t >> 5;
    #pragma unroll
    for (int o = 16; o > 0; o >>= 1) s += __shfl_xor_sync(0xFFFFFFFFu, s, o);
    if (lane == 0) ws[wid] = s;
    __syncthreads();
    if (t == 0) g_bsum[b] = ws[0] + ws[1] + ws[2] + ws[3] + ws[4] + ws[5] + ws[6] + ws[7];
}

__global__ void scan_final_kernel() {
    __shared__ int wtot[32];
    __shared__ int bex[SCAN_BLOCKS];
    int b = blockIdx.x;
    int t = threadIdx.x;             // 1024 threads
    int lane = t & 31, wid = t >> 5;

    if (wid == 0) {
        int v = (lane < SCAN_BLOCKS) ? g_bsum[lane] : 0;
        int incl = v;
        #pragma unroll
        for (int o = 1; o < 32; o <<= 1) {
            int y = __shfl_up_sync(0xFFFFFFFFu, incl, o);
            if (lane >= o) incl += y;
        }
        if (lane < SCAN_BLOCKS) bex[lane] = incl - v;
        int tot = __shfl_sync(0xFFFFFFFFu, incl, 31);
        int v2 = (lane + 32 < SCAN_BLOCKS) ? g_bsum[lane + 32] : 0;
        int incl2 = v2;
        #pragma unroll
        for (int o = 1; o < 32; o <<= 1) {
            int y = __shfl_up_sync(0xFFFFFFFFu, incl2, o);
            if (lane >= o) incl2 += y;
        }
        if (lane + 32 < SCAN_BLOCKS) bex[lane + 32] = tot + incl2 - v2;
    }

    int i = b * 1024 + t;
    int v = (i < N_NODES) ? g_deg[i] : 0;
    int incl = v;
    #pragma unroll
    for (int o = 1; o < 32; o <<= 1) {
        int y = __shfl_up_sync(0xFFFFFFFFu, incl, o);
        if (lane >= o) incl += y;
    }
    if (lane == 31) wtot[wid] = incl;
    __syncthreads();
    if (wid == 0) {
        int w = wtot[lane];
        #pragma unroll
        for (int o = 1; o < 32; o <<= 1) {
            int y = __shfl_up_sync(0xFFFFFFFFu, w, o);
            if (lane >= o) w += y;
        }
        wtot[lane] = w;
    }
    __syncthreads();
    int ex = incl - v + (wid > 0 ? wtot[wid - 1] : 0) + bex[b];
    if (i < N_NODES) {
        g_off[i] = ex;
        g_cur[i] = ex;
    }
    if (b == 0 && t == 0) g_off[N_NODES] = N_EDGES;
}

__global__ void scatter_kernel(const int* __restrict__ ei,
                               const float* __restrict__ ea) {
    int e = blockIdx.x * blockDim.x + threadIdx.x;
    if (e >= N_EDGES) return;
    int s = ei[e];
    int d = ei[N_EDGES + e];
    int pos = atomicAdd(&g_cur[d], 1);
    g_csr_src[pos] = s;
    g_csr_att[pos] = make_float4(ea[e * 3 + 0], ea[e * 3 + 1], ea[e * 3 + 2], 0.f);
}

// ---------------- mma.sync tf32 GEMM, cp.async pipelined ----------------
// A (g_h) and B (g_wtf) are pre-rounded tf32 bit patterns -> raw copies, no cvt.
// write_mode 0: fp16 copy only (layer GEMMs); 1: f32 C only (final GEMM)
#define GBM 128
#define GBN 128
#define GBK 32
#define A_STRIDE 36
#define B_STRIDE 136
#define ASZ (GBM * A_STRIDE)
#define BSZ (GBK * B_STRIDE)
#define GEMM_DSMEM (2 * (ASZ + BSZ) * 4)

__global__ void __launch_bounds__(256, 2)
gemm_mma_kernel(const float* __restrict__ A,
                const float* __restrict__ B,
                const float* __restrict__ bias,
                float* __restrict__ C,
                int M, int write_mode) {
    extern __shared__ uint32_t sm[];

    int tid = threadIdx.x;
    int warp = tid >> 5;
    int lane = tid & 31;
    int wm = warp >> 2;
    int wn = warp & 3;
    int cCol = blockIdx.x;
    int cRow = blockIdx.y;

    uint32_t smem_base = (uint32_t)__cvta_generic_to_shared(sm);

    int arow_base = tid >> 3;            // 0..31
    int acol4 = (tid & 7) * 4;           // 0..28
    int bk = tid >> 5;                   // 0..7
    int bn4 = (tid & 31) * 4;            // 0..124
    const float* Bb = B + cCol * GBN;

    float acc[4][4][4];
    #pragma unroll
    for (int i = 0; i < 4; i++)
        #pragma unroll
        for (int j = 0; j < 4; j++)
            #pragma unroll
            for (int r = 0; r < 4; r++) acc[i][j][r] = 0.f;

    int lr = lane >> 2;
    int lc = lane & 3;

    // async-copy one K-chunk into buffer st
    auto issue_chunk = [&](int chunk, int st) {
        #pragma unroll
        for (int i = 0; i < 4; i++) {
            int row = arow_base + i * 32;
            int grow = cRow * GBM + row;
            bool p = grow < M;
            const float* ga = p ? &A[(long long)grow * 256 + chunk * GBK + acol4] : A;
            uint32_t sa = smem_base + (uint32_t)(st * ASZ + row * A_STRIDE + acol4) * 4u;
            cp16_pred(sa, ga, p);
        }
        #pragma unroll
        for (int i = 0; i < 4; i++) {
            int k = bk + i * 8;
            const float* gb = &Bb[(long long)(chunk * GBK + k) * 256 + bn4];
            uint32_t sb = smem_base + (uint32_t)(2 * ASZ + st * BSZ + k * B_STRIDE + bn4) * 4u;
            cp16(sb, gb);
        }
    };

    issue_chunk(0, 0);
    CP_COMMIT();
    CP_WAIT0();
    __syncthreads();

    for (int kc = 0; kc < 256 / GBK; kc++) {
        int st = kc & 1;
        int nst = st ^ 1;
        if (kc < 7) {
            issue_chunk(kc + 1, nst);
            CP_COMMIT();
        }

        const uint32_t* Asb = sm + st * ASZ;
        const uint32_t* Bsb = sm + 2 * ASZ + st * BSZ;
        #pragma unroll
        for (int ks = 0; ks < GBK / 8; ks++) {
            int k0 = ks * 8;
            uint32_t bf[4][2];
            #pragma unroll
            for (int nt = 0; nt < 4; nt++) {
                int nb = wn * 32 + nt * 8 + lr;
                bf[nt][0] = Bsb[(k0 + lc) * B_STRIDE + nb];
                bf[nt][1] = Bsb[(k0 + lc + 4) * B_STRIDE + nb];
            }
            #pragma unroll
            for (int mt = 0; mt < 4; mt++) {
                int rm = wm * 64 + mt * 16;
                uint32_t a0 = Asb[(rm + lr) * A_STRIDE + k0 + lc];
                uint32_t a1 = Asb[(rm + lr + 8) * A_STRIDE + k0 + lc];
                uint32_t a2 = Asb[(rm + lr) * A_STRIDE + k0 + lc + 4];
                uint32_t a3 = Asb[(rm + lr + 8) * A_STRIDE + k0 + lc + 4];
                #pragma unroll
                for (int nt = 0; nt < 4; nt++) {
                    asm volatile(
                        "mma.sync.aligned.m16n8k8.row.col.f32.tf32.tf32.f32 "
                        "{%0,%1,%2,%3}, {%4,%5,%6,%7}, {%8,%9}, {%0,%1,%2,%3};"
                        : "+f"(acc[mt][nt][0]), "+f"(acc[mt][nt][1]),
                          "+f"(acc[mt][nt][2]), "+f"(acc[mt][nt][3])
                        : "r"(a0), "r"(a1), "r"(a2), "r"(a3),
                          "r"(bf[nt][0]), "r"(bf[nt][1]));
                }
            }
        }
        if (kc < 7) CP_WAIT0();
        __syncthreads();
    }

    // epilogue (+bias): layers -> fp16 copy only; final -> f32 only
    #pragma unroll
    for (int mt = 0; mt < 4; mt++) {
        int row0 = cRow * GBM + wm * 64 + mt * 16 + lr;
        #pragma unroll
        for (int nt = 0; nt < 4; nt++) {
            int col = cCol * GBN + wn * 32 + nt * 8 + lc * 2;
            float b0 = bias[col], b1 = bias[col + 1];
            float2 v0 = make_float2(acc[mt][nt][0] + b0, acc[mt][nt][1] + b1);
            float2 v1 = make_float2(acc[mt][nt][2] + b0, acc[mt][nt][3] + b1);
            if (write_mode == 0) {
                if (row0 < M)
                    *(__half2*)&g_hph[(long long)row0 * 256 + col] = __floats2half2_rn(v0.x, v0.y);
                if (row0 + 8 < M)
                    *(__half2*)&g_hph[(long long)(row0 + 8) * 256 + col] = __floats2half2_rn(v1.x, v1.y);
            } else {
                if (row0 < M)
                    *(float2*)&C[(long long)row0 * 256 + col] = v0;
                if (row0 + 8 < M)
                    *(float2*)&C[(long long)(row0 + 8) * 256 + col] = v1;
            }
        }
    }
}

// ---------------- node attention scores (fp16 input; + per-layer c precompute) ----------------
__global__ void node_score_kernel(const float* __restrict__ as_,
                                  const float* __restrict__ ad_,
                                  const float* __restrict__ We,
                                  const float* __restrict__ ae) {
    if (blockIdx.x == 0 && threadIdx.x < HEADS * 3) {
        int i = threadIdx.x;
        int hh = i / 3, k = i % 3;
        float s = 0.f;
        for (int d = 0; d < HEAD_DIM; d++)
            s += We[k * HIDDEN + hh * HEAD_DIM + d] * ae[hh * HEAD_DIM + d];
        g_c[i] = s;
    }
    int gw = (blockIdx.x * blockDim.x + threadIdx.x) >> 5;
    int lane = threadIdx.x & 31;
    if (gw >= N_NODES * HEADS) return;
    int n = gw >> 2, hh = gw & 3;
    const __half* row = g_hph + (long long)n * HIDDEN + hh * HEAD_DIM;
    float v0 = __half2float(row[lane]), v1 = __half2float(row[lane + 32]);
    float s = v0 * as_[hh * HEAD_DIM + lane] + v1 * as_[hh * HEAD_DIM + lane + 32];
    float t = v0 * ad_[hh * HEAD_DIM + lane] + v1 * ad_[hh * HEAD_DIM + lane + 32];
    #pragma unroll
    for (int o = 16; o > 0; o >>= 1) {
        s += __shfl_xor_sync(0xFFFFFFFFu, s, o);
        t += __shfl_xor_sync(0xFFFFFFFFu, t, o);
    }
    if (lane == 0) {
        g_ss[gw] = s;
        g_sd[gw] = t;
    }
}

// ---------------- fused GAT layer (two-pass): logits+max then exp+agg ----------------
__global__ void gat_fused_kernel() {
    int gw = (blockIdx.x * blockDim.x + threadIdx.x) >> 5;
    int lane = threadIdx.x & 31;
    if (gw >= N_NODES) return;
    int n = gw;
    int r0 = g_off[n], r1 = g_off[n + 1];
    int h = lane >> 3;
    long long hb = (long long)n * HIDDEN + lane * 8;
    float4 hv0 = *(const float4*)&g_h[hb];
    float4 hv1 = *(const float4*)&g_h[hb + 4];

    if (r0 == r1) {
        hv0.x = rtf(elu1(hv0.x)); hv0.y = rtf(elu1(hv0.y));
        hv0.z = rtf(elu1(hv0.z)); hv0.w = rtf(elu1(hv0.w));
        hv1.x = rtf(elu1(hv1.x)); hv1.y = rtf(elu1(hv1.y));
        hv1.z = rtf(elu1(hv1.z)); hv1.w = rtf(elu1(hv1.w));
        *(float4*)&g_h[hb] = hv0;
        *(float4*)&g_h[hb + 4] = hv1;
        return;
    }

    float sd0 = g_sd[n * 4 + 0], sd1 = g_sd[n * 4 + 1];
    float sd2 = g_sd[n * 4 + 2], sd3 = g_sd[n * 4 + 3];
    float c00 = g_c[0], c01 = g_c[1],  c02 = g_c[2];
    float c10 = g_c[3], c11 = g_c[4],  c12 = g_c[5];
    float c20 = g_c[6], c21 = g_c[7],  c22 = g_c[8];
    float c30 = g_c[9], c31 = g_c[10], c32 = g_c[11];

    // pass A: logits + per-head max; store leaky logits for pass B
    float m0 = -INFINITY, m1 = -INFINITY, m2 = -INFINITY, m3 = -INFINITY;
    for (int i = r0 + lane; i < r1; i += 32) {
        int s = g_csr_src[i];
        float4 at = g_csr_att[i];
        float l0 = g_ss[s * 4 + 0] + sd0 + at.x * c00 + at.y * c01 + at.z * c02;
        float l1 = g_ss[s * 4 + 1] + sd1 + at.x * c10 + at.y * c11 + at.z * c12;
        float l2 = g_ss[s * 4 + 2] + sd2 + at.x * c20 + at.y * c21 + at.z * c22;
        float l3 = g_ss[s * 4 + 3] + sd3 + at.x * c30 + at.y * c31 + at.z * c32;
        l0 = l0 > 0.f ? l0 : NEG_SLOPE * l0;
        l1 = l1 > 0.f ? l1 : NEG_SLOPE * l1;
        l2 = l2 > 0.f ? l2 : NEG_SLOPE * l2;
        l3 = l3 > 0.f ? l3 : NEG_SLOPE * l3;
        g_elog[i] = make_float4(l0, l1, l2, l3);
        m0 = fmaxf(m0, l0); m1 = fmaxf(m1, l1);
        m2 = fmaxf(m2, l2); m3 = fmaxf(m3, l3);
    }
    #pragma unroll
    for (int o = 16; o > 0; o >>= 1) {
        m0 = fmaxf(m0, __shfl_xor_sync(0xFFFFFFFFu, m0, o));
        m1 = fmaxf(m1, __shfl_xor_sync(0xFFFFFFFFu, m1, o));
        m2 = fmaxf(m2, __shfl_xor_sync(0xFFFFFFFFu, m2, o));
        m3 = fmaxf(m3, __shfl_xor_sync(0xFFFFFFFFu, m3, o));
    }
    float mh = h == 0 ? m0 : (h == 1 ? m1 : (h == 2 ? m2 : m3));
    __syncwarp();   // make lane-written g_elog visible warp-wide

    // pass B: denom + weighted fp16-row aggregation (unrolled x2 for MLP)
    const float* elog = (const float*)g_elog;
    float4 a0 = make_float4(0.f, 0.f, 0.f, 0.f);
    float4 a1 = make_float4(0.f, 0.f, 0.f, 0.f);
    float den = 0.f;
    int i = r0;
    for (; i + 1 < r1; i += 2) {
        int s0 = g_csr_src[i];
        int s1 = g_csr_src[i + 1];
        float w0 = expf(elog[(long long)i * 4 + h] - mh);
        float w1 = expf(elog[(long long)(i + 1) * 4 + h] - mh);
        uint4 u0 = *(const uint4*)&g_hph[(long long)s0 * HIDDEN + lane * 8];
        uint4 u1 = *(const uint4*)&g_hph[(long long)s1 * HIDDEN + lane * 8];
        den += w0 + w1;
        float2 p;
        p = __half22float2(*(__half2*)&u0.x); a0.x += w0 * p.x; a0.y += w0 * p.y;
        p = __half22float2(*(__half2*)&u0.y); a0.z += w0 * p.x; a0.w += w0 * p.y;
        p = __half22float2(*(__half2*)&u0.z); a1.x += w0 * p.x; a1.y += w0 * p.y;
        p = __half22float2(*(__half2*)&u0.w); a1.z += w0 * p.x; a1.w += w0 * p.y;
        p = __half22float2(*(__half2*)&u1.x); a0.x += w1 * p.x; a0.y += w1 * p.y;
        p = __half22float2(*(__half2*)&u1.y); a0.z += w1 * p.x; a0.w += w1 * p.y;
        p = __half22float2(*(__half2*)&u1.z); a1.x += w1 * p.x; a1.y += w1 * p.y;
        p = __half22float2(*(__half2*)&u1.w); a1.z += w1 * p.x; a1.w += w1 * p.y;
    }
    if (i < r1) {
        int s0 = g_csr_src[i];
        float w0 = expf(elog[(long long)i * 4 + h] - mh);
        uint4 u0 = *(const uint4*)&g_hph[(long long)s0 * HIDDEN + lane * 8];
        den += w0;
        float2 p;
        p = __half22float2(*(__half2*)&u0.x); a0.x += w0 * p.x; a0.y += w0 * p.y;
        p = __half22float2(*(__half2*)&u0.y); a0.z += w0 * p.x; a0.w += w0 * p.y;
        p = __half22float2(*(__half2*)&u0.z); a1.x += w0 * p.x; a1.y += w0 * p.y;
        p = __half22float2(*(__half2*)&u0.w); a1.z += w0 * p.x; a1.w += w0 * p.y;
    }
    float inv = 1.f / fmaxf(den, 1e-16f);
    hv0.x = rtf(elu1(a0.x * inv + hv0.x)); hv0.y = rtf(elu1(a0.y * inv + hv0.y));
    hv0.z = rtf(elu1(a0.z * inv + hv0.z)); hv0.w = rtf(elu1(a0.w * inv + hv0.w));
    hv1.x = rtf(elu1(a1.x * inv + hv1.x)); hv1.y = rtf(elu1(a1.y * inv + hv1.y));
    hv1.z = rtf(elu1(a1.z * inv + hv1.z)); hv1.w = rtf(elu1(a1.w * inv + hv1.w));
    *(float4*)&g_h[hb] = hv0;
    *(float4*)&g_h[hb + 4] = hv1;
}

// ---------------- output LN + ELU + write node_emb + pool ----------------
__global__ void ln_out_kernel(const float* __restrict__ lg,
                              const float* __restrict__ lb,
                              const int* __restrict__ batch,
                              float* __restrict__ node_out) {
    int n = blockIdx.x;
    int j = threadIdx.x;
    __shared__ float ws[8];
    float y = g_hp[(long long)n * HIDDEN + j];
    float mu = block_sum_256(y, ws) * (1.f / HIDDEN);
    float d = y - mu;
    float var = block_sum_256(d * d, ws) * (1.f / HIDDEN);
    float v = elu1(d * rsqrtf(var + 1e-5f) * lg[j] + lb[j]);
    node_out[(long long)n * HIDDEN + j] = v;
    int b = batch[n];
    atomicAdd(&g_pool[b * HIDDEN + j], v);
    if (j == 0) atomicAdd(&g_cnt[b], 1.0f);
}

// ---------------- graph mean pool output ----------------
__global__ void graph_out_kernel(float* __restrict__ out) {
    int i = blockIdx.x * blockDim.x + threadIdx.x;
    if (i < NUM_GRAPHS * HIDDEN) out[i] = g_pool[i] / fmaxf(g_cnt[i >> 8], 1.0f);
}

// ---------------- launch ----------------
extern "C" void kernel_launch(void* const* d_in, const int* in_sizes, int n_in,
                              void* d_out, int out_size) {
    const float* x          = (const float*)d_in[0];
    const int*   edge_index = (const int*)d_in[1];
    const float* edge_attr  = (const float*)d_in[2];
    const int*   batch      = (const int*)d_in[3];
    const float* W_in       = (const float*)d_in[4];
    const float* b_in       = (const float*)d_in[5];
    const float* ln_in_g    = (const float*)d_in[6];
    const float* ln_in_b    = (const float*)d_in[7];
    const float* W_gat      = (const float*)d_in[8];
    const float* b_gat      = (const float*)d_in[9];
    const float* W_e        = (const float*)d_in[10];
    const float* a_src      = (const float*)d_in[11];
    const float* a_dst      = (const float*)d_in[12];
    const float* a_edge     = (const float*)d_in[13];
    const float* W_out      = (const float*)d_in[14];
    const float* b_out      = (const float*)d_in[15];
    const float* ln_out_g   = (const float*)d_in[16];
    const float* ln_out_b   = (const float*)d_in[17];

    float* out = (float*)d_out;

    float *hp_, *h_, *wtf_;
    cudaGetSymbolAddress((void**)&h_, g_h);
    cudaGetSymbolAddress((void**)&hp_, g_hp);
    cudaGetSymbolAddress((void**)&wtf_, g_wtf);

    long long node_off = (long long)out_size - (long long)N_NODES * HIDDEN;
    float* node_out = (node_off >= 0) ? out + node_off : hp_;

    static int smem_set = 0;
    if (!smem_set) {
        cudaFuncSetAttribute(gemm_mma_kernel, cudaFuncAttributeMaxDynamicSharedMemorySize,
                             GEMM_DSMEM);
        smem_set = 1;
    }

    prep_w_kernel<<<256, 256>>>(W_gat, W_out);
    init_kernel<<<(N_NODES + 255) / 256, 256>>>();
    input_proj_kernel<<<N_NODES, HIDDEN>>>(x, W_in, b_in, ln_in_g, ln_in_b);
    hist_kernel<<<(N_EDGES + 255) / 256, 256>>>(edge_index);
    scan_reduce_kernel<<<SCAN_BLOCKS, 256>>>();
    scan_final_kernel<<<SCAN_BLOCKS, 1024>>>();
    scatter_kernel<<<(N_EDGES + 255) / 256, 256>>>(edge_index, edge_attr);

    dim3 gemm_grid(2, (N_NODES + GBM - 1) / GBM);
    int score_blocks = (N_NODES * HEADS * 32 + 255) / 256;
    int gat_blocks = (N_NODES * 32 + 255) / 256;

    for (int l = 0; l < LAYERS; l++) {
        const float* Wl  = wtf_ + (long long)l * HIDDEN * HIDDEN;
        const float* bl  = b_gat + l * HIDDEN;
        const float* Wel = W_e + l * 3 * HIDDEN;
        const float* asl = a_src + l * HEADS * HEAD_DIM;
        const float* adl = a_dst + l * HEADS * HEAD_DIM;
        const float* ael = a_edge + l * HEADS * HEAD_DIM;

        gemm_mma_kernel<<<gemm_grid, 256, GEMM_DSMEM>>>(h_, Wl, bl, hp_, N_NODES, 0);
        node_score_kernel<<<score_blocks, 256>>>(asl, adl, Wel, ael);
        gat_fused_kernel<<<gat_blocks, 256>>>();
    }

    gemm_mma_kernel<<<gemm_grid, 256, GEMM_DSMEM>>>(wtf_ ? h_ : h_, wtf_ + 3LL * HIDDEN * HIDDEN,
                                                    b_out, hp_, N_NODES, 1);
    ln_out_kernel<<<N_NODES, HIDDEN>>>(ln_out_g, ln_out_b, batch, node_out);
    graph_out_kernel<<<(NUM_GRAPHS * HIDDEN + 255) / 256, 256>>>(out);
}

// round 16
// speedup vs baseline: 1.3248x; 1.0773x over previous
#include <cuda_runtime.h>
#include <cuda_bf16.h>
#include <cuda_fp16.h>
#include <math.h>
#include <stdint.h>

#define N_NODES 50000
#define N_EDGES 800000
#define HIDDEN  256
#define HEADS   4
#define HEAD_DIM 64
#define LAYERS  3
#define NUM_GRAPHS 64
#define NEG_SLOPE 0.2f
#define SCAN_BLOCKS ((N_NODES + 1023) / 1024)   // 49

// ---------------- scratch (device globals; no allocation allowed) ----------------
__device__ float  g_h   [(long long)N_NODES * HIDDEN];   // tf32-rounded activations
__device__ float  g_hp  [(long long)N_NODES * HIDDEN];
__device__ __half g_hph [(long long)N_NODES * HIDDEN];   // fp16 copy of projections for gathers
__device__ float  g_wtf [4 * HIDDEN * HIDDEN];           // tf32-rounded weights (3 GAT + out)
__device__ float  g_ss  [N_NODES * HEADS];
__device__ float  g_sd  [N_NODES * HEADS];
__device__ float  g_c   [LAYERS * HEADS * 3];            // per-layer edge-attr coefficients
__device__ float  g_pool[NUM_GRAPHS * HIDDEN];
__device__ float  g_cnt [NUM_GRAPHS];
// CSR scratch
__device__ int    g_deg[N_NODES];
__device__ int    g_off[N_NODES + 1];
__device__ int    g_cur[N_NODES];
__device__ int    g_bsum[SCAN_BLOCKS];
__device__ int    g_csr_src[N_EDGES];
__device__ float4 g_csr_att[N_EDGES];
__device__ float4 g_elog[N_EDGES];                       // per-layer leaky logits (4 heads)

// ---------------- helpers ----------------
__device__ __forceinline__ float elu1(float v) {
    return v > 0.f ? v : expm1f(v);
}

__device__ __forceinline__ uint32_t f2tf32(float x) {
    uint32_t u;
    asm("cvt.rna.tf32.f32 %0, %1;" : "=r"(u) : "f"(x));
    return u;
}

__device__ __forceinline__ float rtf(float x) {        // tf32-rounded float
    return __uint_as_float(f2tf32(x));
}

__device__ __forceinline__ void cp16(uint32_t saddr, const void* g) {
    asm volatile("cp.async.cg.shared.global [%0], [%1], 16;" :: "r"(saddr), "l"(g));
}
__device__ __forceinline__ void cp16_pred(uint32_t saddr, const void* g, bool p) {
    int sz = p ? 16 : 0;
    asm volatile("cp.async.cg.shared.global [%0], [%1], 16, %2;" :: "r"(saddr), "l"(g), "r"(sz));
}
#define CP_COMMIT() asm volatile("cp.async.commit_group;" ::: "memory")
#define CP_WAIT0()  asm volatile("cp.async.wait_group 0;" ::: "memory")

// ---------------- weight pre-round + per-layer c coefficients (once) ----------------
__global__ void prep_w_kernel(const float* __restrict__ Wg, const float* __restrict__ Wo,
                              const float* __restrict__ We, const float* __restrict__ ae) {
    int i = blockIdx.x * blockDim.x + threadIdx.x;     // float4 index
    if (i < 65536) {
        long long f = (long long)i * 4;
        float4 v = (f < 196608) ? *(const float4*)(Wg + f)
                                : *(const float4*)(Wo + (f - 196608));
        uint4 r = make_uint4(f2tf32(v.x), f2tf32(v.y), f2tf32(v.z), f2tf32(v.w));
        ((uint4*)g_wtf)[i] = r;
    }
    if (blockIdx.x == 0 && threadIdx.x < LAYERS * 12) {
        int l = threadIdx.x / 12, r = threadIdx.x % 12;
        int hh = r / 3, k = r % 3;
        float s = 0.f;
        for (int d = 0; d < HEAD_DIM; d++)
            s += We[l * 3 * HIDDEN + k * HIDDEN + hh * HEAD_DIM + d]
               * ae[l * HEADS * HEAD_DIM + hh * HEAD_DIM + d];
        g_c[l * 12 + r] = s;
    }
}

// ---------------- init: pooling accumulators + degree histogram ----------------
__global__ void init_kernel() {
    int i = blockIdx.x * blockDim.x + threadIdx.x;
    if (i < NUM_GRAPHS * HIDDEN) g_pool[i] = 0.f;
    if (i < NUM_GRAPHS) g_cnt[i] = 0.f;
    if (i < N_NODES) g_deg[i] = 0;
}

// ---------------- block LN reduce helper (256 threads) ----------------
__device__ __forceinline__ float block_sum_256(float v, float* ws) {
    int lane = threadIdx.x & 31, wid = threadIdx.x >> 5;
    #pragma unroll
    for (int o = 16; o > 0; o >>= 1) v += __shfl_xor_sync(0xFFFFFFFFu, v, o);
    if (lane == 0) ws[wid] = v;
    __syncthreads();
    float s = ws[0] + ws[1] + ws[2] + ws[3] + ws[4] + ws[5] + ws[6] + ws[7];
    __syncthreads();
    return s;
}

// ---------------- input projection + LN + ELU (writes tf32-rounded h) ----------------
__global__ void input_proj_kernel(const float* __restrict__ x,
                                  const float* __restrict__ Win,
                                  const float* __restrict__ bin,
                                  const float* __restrict__ lg,
                                  const float* __restrict__ lb) {
    int n = blockIdx.x;
    int j = threadIdx.x;
    __shared__ float xs[8];
    __shared__ float ws[8];
    if (j < 8) xs[j] = x[n * 8 + j];
    __syncthreads();
    float y = bin[j];
    #pragma unroll
    for (int k = 0; k < 8; k++) y += xs[k] * Win[k * HIDDEN + j];
    float mu = block_sum_256(y, ws) * (1.f / HIDDEN);
    float d = y - mu;
    float var = block_sum_256(d * d, ws) * (1.f / HIDDEN);
    float v = d * rsqrtf(var + 1e-5f) * lg[j] + lb[j];
    g_h[(long long)n * HIDDEN + j] = rtf(elu1(v));
}

// ---------------- CSR build ----------------
__global__ void hist_kernel(const int* __restrict__ ei) {
    int e = blockIdx.x * blockDim.x + threadIdx.x;
    if (e >= N_EDGES) return;
    atomicAdd(&g_deg[ei[N_EDGES + e]], 1);
}

__global__ void scan_reduce_kernel() {
    __shared__ int ws[8];
    int b = blockIdx.x;
    int t = threadIdx.x;             // 256 threads
    int base = b * 1024;
    int s = 0;
    #pragma unroll
    for (int i = 0; i < 4; i++) {
        int idx = base + t + i * 256;
        if (idx < N_NODES) s += g_deg[idx];
    }
    int lane = t & 31, wid = t >> 5;
    #pragma unroll
    for (int o = 16; o > 0; o >>= 1) s += __shfl_xor_sync(0xFFFFFFFFu, s, o);
    if (lane == 0) ws[wid] = s;
    __syncthreads();
    if (t == 0) g_bsum[b] = ws[0] + ws[1] + ws[2] + ws[3] + ws[4] + ws[5] + ws[6] + ws[7];
}

__global__ void scan_final_kernel() {
    __shared__ int wtot[32];
    __shared__ int bex[SCAN_BLOCKS];
    int b = blockIdx.x;
    int t = threadIdx.x;             // 1024 threads
    int lane = t & 31, wid = t >> 5;

    if (wid == 0) {
        int v = (lane < SCAN_BLOCKS) ? g_bsum[lane] : 0;
        int incl = v;
        #pragma unroll
        for (int o = 1; o < 32; o <<= 1) {
            int y = __shfl_up_sync(0xFFFFFFFFu, incl, o);
            if (lane >= o) incl += y;
        }
        if (lane < SCAN_BLOCKS) bex[lane] = incl - v;
        int tot = __shfl_sync(0xFFFFFFFFu, incl, 31);
        int v2 = (lane + 32 < SCAN_BLOCKS) ? g_bsum[lane + 32] : 0;
        int incl2 = v2;
        #pragma unroll
        for (int o = 1; o < 32; o <<= 1) {
            int y = __shfl_up_sync(0xFFFFFFFFu, incl2, o);
            if (lane >= o) incl2 += y;
        }
        if (lane + 32 < SCAN_BLOCKS) bex[lane + 32] = tot + incl2 - v2;
    }

    int i = b * 1024 + t;
    int v = (i < N_NODES) ? g_deg[i] : 0;
    int incl = v;
    #pragma unroll
    for (int o = 1; o < 32; o <<= 1) {
        int y = __shfl_up_sync(0xFFFFFFFFu, incl, o);
        if (lane >= o) incl += y;
    }
    if (lane == 31) wtot[wid] = incl;
    __syncthreads();
    if (wid == 0) {
        int w = wtot[lane];
        #pragma unroll
        for (int o = 1; o < 32; o <<= 1) {
            int y = __shfl_up_sync(0xFFFFFFFFu, w, o);
            if (lane >= o) w += y;
        }
        wtot[lane] = w;
    }
    __syncthreads();
    int ex = incl - v + (wid > 0 ? wtot[wid - 1] : 0) + bex[b];
    if (i < N_NODES) {
        g_off[i] = ex;
        g_cur[i] = ex;
    }
    if (b == 0 && t == 0) g_off[N_NODES] = N_EDGES;
}

__global__ void scatter_kernel(const int* __restrict__ ei,
                               const float* __restrict__ ea) {
    int e = blockIdx.x * blockDim.x + threadIdx.x;
    if (e >= N_EDGES) return;
    int s = ei[e];
    int d = ei[N_EDGES + e];
    int pos = atomicAdd(&g_cur[d], 1);
    g_csr_src[pos] = s;
    g_csr_att[pos] = make_float4(ea[e * 3 + 0], ea[e * 3 + 1], ea[e * 3 + 2], 0.f);
}

// ---------------- mma.sync tf32 GEMM, cp.async pipelined, fused score epilogue ----------
// write_mode 0: fp16 copy + node scores (layer GEMMs); 1: f32 C only (final GEMM)
#define GBM 128
#define GBN 128
#define GBK 32
#define A_STRIDE 36
#define B_STRIDE 136
#define ASZ (GBM * A_STRIDE)
#define BSZ (GBK * B_STRIDE)
#define GEMM_DSMEM (2 * (ASZ + BSZ) * 4)

__global__ void __launch_bounds__(256, 2)
gemm_mma_kernel(const float* __restrict__ A,
                const float* __restrict__ B,
                const float* __restrict__ bias,
                const float* __restrict__ asv,
                const float* __restrict__ adv,
                float* __restrict__ C,
                int M, int write_mode) {
    extern __shared__ uint32_t sm[];

    int tid = threadIdx.x;
    int warp = tid >> 5;
    int lane = tid & 31;
    int wm = warp >> 2;
    int wn = warp & 3;
    int cCol = blockIdx.x;
    int cRow = blockIdx.y;

    uint32_t smem_base = (uint32_t)__cvta_generic_to_shared(sm);

    int arow_base = tid >> 3;            // 0..31
    int acol4 = (tid & 7) * 4;           // 0..28
    int bk = tid >> 5;                   // 0..7
    int bn4 = (tid & 31) * 4;            // 0..124
    const float* Bb = B + cCol * GBN;

    float acc[4][4][4];
    #pragma unroll
    for (int i = 0; i < 4; i++)
        #pragma unroll
        for (int j = 0; j < 4; j++)
            #pragma unroll
            for (int r = 0; r < 4; r++) acc[i][j][r] = 0.f;

    int lr = lane >> 2;
    int lc = lane & 3;

    auto issue_chunk = [&](int chunk, int st) {
        #pragma unroll
        for (int i = 0; i < 4; i++) {
            int row = arow_base + i * 32;
            int grow = cRow * GBM + row;
            bool p = grow < M;
            const float* ga = p ? &A[(long long)grow * 256 + chunk * GBK + acol4] : A;
            uint32_t sa = smem_base + (uint32_t)(st * ASZ + row * A_STRIDE + acol4) * 4u;
            cp16_pred(sa, ga, p);
        }
        #pragma unroll
        for (int i = 0; i < 4; i++) {
            int k = bk + i * 8;
            const float* gb = &Bb[(long long)(chunk * GBK + k) * 256 + bn4];
            uint32_t sb = smem_base + (uint32_t)(2 * ASZ + st * BSZ + k * B_STRIDE + bn4) * 4u;
            cp16(sb, gb);
        }
    };

    issue_chunk(0, 0);
    CP_COMMIT();
    CP_WAIT0();
    __syncthreads();

    for (int kc = 0; kc < 256 / GBK; kc++) {
        int st = kc & 1;
        int nst = st ^ 1;
        if (kc < 7) {
            issue_chunk(kc + 1, nst);
            CP_COMMIT();
        }

        const uint32_t* Asb = sm + st * ASZ;
        const uint32_t* Bsb = sm + 2 * ASZ + st * BSZ;
        #pragma unroll
        for (int ks = 0; ks < GBK / 8; ks++) {
            int k0 = ks * 8;
            uint32_t bf[4][2];
            #pragma unroll
            for (int nt = 0; nt < 4; nt++) {
                int nb = wn * 32 + nt * 8 + lr;
                bf[nt][0] = Bsb[(k0 + lc) * B_STRIDE + nb];
                bf[nt][1] = Bsb[(k0 + lc + 4) * B_STRIDE + nb];
            }
            #pragma unroll
            for (int mt = 0; mt < 4; mt++) {
                int rm = wm * 64 + mt * 16;
                uint32_t a0 = Asb[(rm + lr) * A_STRIDE + k0 + lc];
                uint32_t a1 = Asb[(rm + lr + 8) * A_STRIDE + k0 + lc];
                uint32_t a2 = Asb[(rm + lr) * A_STRIDE + k0 + lc + 4];
                uint32_t a3 = Asb[(rm + lr + 8) * A_STRIDE + k0 + lc + 4];
                #pragma unroll
                for (int nt = 0; nt < 4; nt++) {
                    asm volatile(
                        "mma.sync.aligned.m16n8k8.row.col.f32.tf32.tf32.f32 "
                        "{%0,%1,%2,%3}, {%4,%5,%6,%7}, {%8,%9}, {%0,%1,%2,%3};"
                        : "+f"(acc[mt][nt][0]), "+f"(acc[mt][nt][1]),
                          "+f"(acc[mt][nt][2]), "+f"(acc[mt][nt][3])
                        : "r"(a0), "r"(a1), "r"(a2), "r"(a3),
                          "r"(bf[nt][0]), "r"(bf[nt][1]));
                }
            }
        }
        if (kc < 7) CP_WAIT0();
        __syncthreads();
    }

    if (write_mode == 0) {
        // fused epilogue: fp16 copy + per-(row,head) attention scores
        float* scbuf = (float*)sm;     // [wnpar(2)][head_local(2)][row(128)][ss,sd]
        float as0[4], as1[4], ad0[4], ad1[4];
        #pragma unroll
        for (int nt = 0; nt < 4; nt++) {
            int col = cCol * GBN + wn * 32 + nt * 8 + lc * 2;
            int hg = col >> 6, d = col & 63;
            as0[nt] = asv[hg * 64 + d];
            as1[nt] = asv[hg * 64 + d + 1];
            ad0[nt] = adv[hg * 64 + d];
            ad1[nt] = adv[hg * 64 + d + 1];
        }
        #pragma unroll
        for (int mt = 0; mt < 4; mt++) {
            int row0 = cRow * GBM + wm * 64 + mt * 16 + lr;
            float pss0 = 0.f, psd0 = 0.f, pss1 = 0.f, psd1 = 0.f;
            #pragma unroll
            for (int nt = 0; nt < 4; nt++) {
                int col = cCol * GBN + wn * 32 + nt * 8 + lc * 2;
                float b0 = bias[col], b1 = bias[col + 1];
                float v00 = acc[mt][nt][0] + b0, v01 = acc[mt][nt][1] + b1;
                float v10 = acc[mt][nt][2] + b0, v11 = acc[mt][nt][3] + b1;
                if (row0 < M)
                    *(__half2*)&g_hph[(long long)row0 * 256 + col] = __floats2half2_rn(v00, v01);
                if (row0 + 8 < M)
                    *(__half2*)&g_hph[(long long)(row0 + 8) * 256 + col] = __floats2half2_rn(v10, v11);
                pss0 += v00 * as0[nt] + v01 * as1[nt];
                psd0 += v00 * ad0[nt] + v01 * ad1[nt];
                pss1 += v10 * as0[nt] + v11 * as1[nt];
                psd1 += v10 * ad0[nt] + v11 * ad1[nt];
            }
            #pragma unroll
            for (int o = 1; o <= 2; o <<= 1) {
                pss0 += __shfl_xor_sync(0xFFFFFFFFu, pss0, o);
                psd0 += __shfl_xor_sync(0xFFFFFFFFu, psd0, o);
                pss1 += __shfl_xor_sync(0xFFFFFFFFu, pss1, o);
                psd1 += __shfl_xor_sync(0xFFFFFFFFu, psd1, o);
            }
            if (lc == 0) {
                int slot = (wn & 1) * 2 + (wn >> 1);
                int rl0 = wm * 64 + mt * 16 + lr;
                scbuf[(slot * 128 + rl0) * 2 + 0] = pss0;
                scbuf[(slot * 128 + rl0) * 2 + 1] = psd0;
                scbuf[(slot * 128 + rl0 + 8) * 2 + 0] = pss1;
                scbuf[(slot * 128 + rl0 + 8) * 2 + 1] = psd1;
            }
        }
        __syncthreads();
        {
            int hl = tid >> 7, row = tid & 127;
            // slots: wnpar0 -> hl, wnpar1 -> hl  => slot indices hl and 2+hl
            float ss = scbuf[((hl) * 128 + row) * 2 + 0] + scbuf[((2 + hl) * 128 + row) * 2 + 0];
            float sd = scbuf[((hl) * 128 + row) * 2 + 1] + scbuf[((2 + hl) * 128 + row) * 2 + 1];
            int grow = cRow * GBM + row;
            if (grow < M) {
                int hg = cCol * 2 + hl;
                g_ss[grow * 4 + hg] = ss;
                g_sd[grow * 4 + hg] = sd;
            }
        }
    } else {
        #pragma unroll
        for (int mt = 0; mt < 4; mt++) {
            int row0 = cRow * GBM + wm * 64 + mt * 16 + lr;
            #pragma unroll
            for (int nt = 0; nt < 4; nt++) {
                int col = cCol * GBN + wn * 32 + nt * 8 + lc * 2;
                float b0 = bias[col], b1 = bias[col + 1];
                float2 v0 = make_float2(acc[mt][nt][0] + b0, acc[mt][nt][1] + b1);
                float2 v1 = make_float2(acc[mt][nt][2] + b0, acc[mt][nt][3] + b1);
                if (row0 < M)
                    *(float2*)&C[(long long)row0 * 256 + col] = v0;
                if (row0 + 8 < M)
                    *(float2*)&C[(long long)(row0 + 8) * 256 + col] = v1;
            }
        }
    }
}

// ---------------- fused GAT layer (two-pass): logits+max then exp+agg ----------------
__global__ void gat_fused_kernel(const float* __restrict__ cv) {
    int gw = (blockIdx.x * blockDim.x + threadIdx.x) >> 5;
    int lane = threadIdx.x & 31;
    if (gw >= N_NODES) return;
    int n = gw;
    int r0 = g_off[n], r1 = g_off[n + 1];
    int h = lane >> 3;
    long long hb = (long long)n * HIDDEN + lane * 8;
    float4 hv0 = *(const float4*)&g_h[hb];
    float4 hv1 = *(const float4*)&g_h[hb + 4];

    if (r0 == r1) {
        hv0.x = rtf(elu1(hv0.x)); hv0.y = rtf(elu1(hv0.y));
        hv0.z = rtf(elu1(hv0.z)); hv0.w = rtf(elu1(hv0.w));
        hv1.x = rtf(elu1(hv1.x)); hv1.y = rtf(elu1(hv1.y));
        hv1.z = rtf(elu1(hv1.z)); hv1.w = rtf(elu1(hv1.w));
        *(float4*)&g_h[hb] = hv0;
        *(float4*)&g_h[hb + 4] = hv1;
        return;
    }

    float sd0 = g_sd[n * 4 + 0], sd1 = g_sd[n * 4 + 1];
    float sd2 = g_sd[n * 4 + 2], sd3 = g_sd[n * 4 + 3];
    float c00 = cv[0], c01 = cv[1],  c02 = cv[2];
    float c10 = cv[3], c11 = cv[4],  c12 = cv[5];
    float c20 = cv[6], c21 = cv[7],  c22 = cv[8];
    float c30 = cv[9], c31 = cv[10], c32 = cv[11];

    // pass A: logits + per-head max; store leaky logits for pass B
    float m0 = -INFINITY, m1 = -INFINITY, m2 = -INFINITY, m3 = -INFINITY;
    for (int i = r0 + lane; i < r1; i += 32) {
        int s = g_csr_src[i];
        float4 at = g_csr_att[i];
        float l0 = g_ss[s * 4 + 0] + sd0 + at.x * c00 + at.y * c01 + at.z * c02;
        float l1 = g_ss[s * 4 + 1] + sd1 + at.x * c10 + at.y * c11 + at.z * c12;
        float l2 = g_ss[s * 4 + 2] + sd2 + at.x * c20 + at.y * c21 + at.z * c22;
        float l3 = g_ss[s * 4 + 3] + sd3 + at.x * c30 + at.y * c31 + at.z * c32;
        l0 = l0 > 0.f ? l0 : NEG_SLOPE * l0;
        l1 = l1 > 0.f ? l1 : NEG_SLOPE * l1;
        l2 = l2 > 0.f ? l2 : NEG_SLOPE * l2;
        l3 = l3 > 0.f ? l3 : NEG_SLOPE * l3;
        g_elog[i] = make_float4(l0, l1, l2, l3);
        m0 = fmaxf(m0, l0); m1 = fmaxf(m1, l1);
        m2 = fmaxf(m2, l2); m3 = fmaxf(m3, l3);
    }
    #pragma unroll
    for (int o = 16; o > 0; o >>= 1) {
        m0 = fmaxf(m0, __shfl_xor_sync(0xFFFFFFFFu, m0, o));
        m1 = fmaxf(m1, __shfl_xor_sync(0xFFFFFFFFu, m1, o));
        m2 = fmaxf(m2, __shfl_xor_sync(0xFFFFFFFFu, m2, o));
        m3 = fmaxf(m3, __shfl_xor_sync(0xFFFFFFFFu, m3, o));
    }
    float mh = h == 0 ? m0 : (h == 1 ? m1 : (h == 2 ? m2 : m3));
    __syncwarp();   // make lane-written g_elog visible warp-wide

    // pass B: denom + weighted fp16-row aggregation (unrolled x2 for MLP)
    const float* elog = (const float*)g_elog;
    float4 a0 = make_float4(0.f, 0.f, 0.f, 0.f);
    float4 a1 = make_float4(0.f, 0.f, 0.f, 0.f);
    float den = 0.f;
    int i = r0;
    for (; i + 1 < r1; i += 2) {
        int s0 = g_csr_src[i];
        int s1 = g_csr_src[i + 1];
        float w0 = expf(elog[(long long)i * 4 + h] - mh);
        float w1 = expf(elog[(long long)(i + 1) * 4 + h] - mh);
        uint4 u0 = *(const uint4*)&g_hph[(long long)s0 * HIDDEN + lane * 8];
        uint4 u1 = *(const uint4*)&g_hph[(long long)s1 * HIDDEN + lane * 8];
        den += w0 + w1;
        float2 p;
        p = __half22float2(*(__half2*)&u0.x); a0.x += w0 * p.x; a0.y += w0 * p.y;
        p = __half22float2(*(__half2*)&u0.y); a0.z += w0 * p.x; a0.w += w0 * p.y;
        p = __half22float2(*(__half2*)&u0.z); a1.x += w0 * p.x; a1.y += w0 * p.y;
        p = __half22float2(*(__half2*)&u0.w); a1.z += w0 * p.x; a1.w += w0 * p.y;
        p = __half22float2(*(__half2*)&u1.x); a0.x += w1 * p.x; a0.y += w1 * p.y;
        p = __half22float2(*(__half2*)&u1.y); a0.z += w1 * p.x; a0.w += w1 * p.y;
        p = __half22float2(*(__half2*)&u1.z); a1.x += w1 * p.x; a1.y += w1 * p.y;
        p = __half22float2(*(__half2*)&u1.w); a1.z += w1 * p.x; a1.w += w1 * p.y;
    }
    if (i < r1) {
        int s0 = g_csr_src[i];
        float w0 = expf(elog[(long long)i * 4 + h] - mh);
        uint4 u0 = *(const uint4*)&g_hph[(long long)s0 * HIDDEN + lane * 8];
        den += w0;
        float2 p;
        p = __half22float2(*(__half2*)&u0.x); a0.x += w0 * p.x; a0.y += w0 * p.y;
        p = __half22float2(*(__half2*)&u0.y); a0.z += w0 * p.x; a0.w += w0 * p.y;
        p = __half22float2(*(__half2*)&u0.z); a1.x += w0 * p.x; a1.y += w0 * p.y;
        p = __half22float2(*(__half2*)&u0.w); a1.z += w0 * p.x; a1.w += w0 * p.y;
    }
    float inv = 1.f / fmaxf(den, 1e-16f);
    hv0.x = rtf(elu1(a0.x * inv + hv0.x)); hv0.y = rtf(elu1(a0.y * inv + hv0.y));
    hv0.z = rtf(elu1(a0.z * inv + hv0.z)); hv0.w = rtf(elu1(a0.w * inv + hv0.w));
    hv1.x = rtf(elu1(a1.x * inv + hv1.x)); hv1.y = rtf(elu1(a1.y * inv + hv1.y));
    hv1.z = rtf(elu1(a1.z * inv + hv1.z)); hv1.w = rtf(elu1(a1.w * inv + hv1.w));
    *(float4*)&g_h[hb] = hv0;
    *(float4*)&g_h[hb + 4] = hv1;
}

// ---------------- output LN + ELU + write node_emb + pool ----------------
__global__ void ln_out_kernel(const float* __restrict__ lg,
                              const float* __restrict__ lb,
                              const int* __restrict__ batch,
                              float* __restrict__ node_out) {
    int n = blockIdx.x;
    int j = threadIdx.x;
    __shared__ float ws[8];
    float y = g_hp[(long long)n * HIDDEN + j];
    float mu = block_sum_256(y, ws) * (1.f / HIDDEN);
    float d = y - mu;
    float var = block_sum_256(d * d, ws) * (1.f / HIDDEN);
    float v = elu1(d * rsqrtf(var + 1e-5f) * lg[j] + lb[j]);
    node_out[(long long)n * HIDDEN + j] = v;
    int b = batch[n];
    atomicAdd(&g_pool[b * HIDDEN + j], v);
    if (j == 0) atomicAdd(&g_cnt[b], 1.0f);
}

// ---------------- graph mean pool output ----------------
__global__ void graph_out_kernel(float* __restrict__ out) {
    int i = blockIdx.x * blockDim.x + threadIdx.x;
    if (i < NUM_GRAPHS * HIDDEN) out[i] = g_pool[i] / fmaxf(g_cnt[i >> 8], 1.0f);
}

// ---------------- launch ----------------
extern "C" void kernel_launch(void* const* d_in, const int* in_sizes, int n_in,
                              void* d_out, int out_size) {
    const float* x          = (const float*)d_in[0];
    const int*   edge_index = (const int*)d_in[1];
    const float* edge_attr  = (const float*)d_in[2];
    const int*   batch      = (const int*)d_in[3];
    const float* W_in       = (const float*)d_in[4];
    const float* b_in       = (const float*)d_in[5];
    const float* ln_in_g    = (const float*)d_in[6];
    const float* ln_in_b    = (const float*)d_in[7];
    const float* W_gat      = (const float*)d_in[8];
    const float* b_gat      = (const float*)d_in[9];
    const float* W_e        = (const float*)d_in[10];
    const float* a_src      = (const float*)d_in[11];
    const float* a_dst      = (const float*)d_in[12];
    const float* a_edge     = (const float*)d_in[13];
    const float* W_out      = (const float*)d_in[14];
    const float* b_out      = (const float*)d_in[15];
    const float* ln_out_g   = (const float*)d_in[16];
    const float* ln_out_b   = (const float*)d_in[17];

    float* out = (float*)d_out;

    float *hp_, *h_, *wtf_, *c_;
    cudaGetSymbolAddress((void**)&h_, g_h);
    cudaGetSymbolAddress((void**)&hp_, g_hp);
    cudaGetSymbolAddress((void**)&wtf_, g_wtf);
    cudaGetSymbolAddress((void**)&c_, g_c);

    long long node_off = (long long)out_size - (long long)N_NODES * HIDDEN;
    float* node_out = (node_off >= 0) ? out + node_off : hp_;

    static int smem_set = 0;
    if (!smem_set) {
        cudaFuncSetAttribute(gemm_mma_kernel, cudaFuncAttributeMaxDynamicSharedMemorySize,
                             GEMM_DSMEM);
        smem_set = 1;
    }

    dim3 gemm_grid(2, (N_NODES + GBM - 1) / GBM);
    int gat_blocks = (N_NODES * 32 + 255) / 256;

    // launch order arranged so the first GEMM is launch index 5 (ncu -s 5 -c 1)
    prep_w_kernel<<<256, 256>>>(W_gat, W_out, W_e, a_edge);                        // 0
    init_kernel<<<(N_NODES + 255) / 256, 256>>>();                                // 1
    input_proj_kernel<<<N_NODES, HIDDEN>>>(x, W_in, b_in, ln_in_g, ln_in_b);      // 2
    hist_kernel<<<(N_EDGES + 255) / 256, 256>>>(edge_index);                      // 3
    scan_reduce_kernel<<<SCAN_BLOCKS, 256>>>();                                   // 4
    gemm_mma_kernel<<<gemm_grid, 256, GEMM_DSMEM>>>(                              // 5 (profiled)
        h_, wtf_, b_gat, a_src, a_dst, hp_, N_NODES, 0);
    scan_final_kernel<<<SCAN_BLOCKS, 1024>>>();                                   // 6
    scatter_kernel<<<(N_EDGES + 255) / 256, 256>>>(edge_index, edge_attr);        // 7

    for (int l = 0; l < LAYERS; l++) {
        if (l > 0) {
            gemm_mma_kernel<<<gemm_grid, 256, GEMM_DSMEM>>>(
                h_, wtf_ + (long long)l * HIDDEN * HIDDEN, b_gat + l * HIDDEN,
                a_src + l * HEADS * HEAD_DIM, a_dst + l * HEADS * HEAD_DIM,
                hp_, N_NODES, 0);
        }
        gat_fused_kernel<<<gat_blocks, 256>>>(c_ + l * 12);
    }

    gemm_mma_kernel<<<gemm_grid, 256, GEMM_DSMEM>>>(
        h_, wtf_ + 3LL * HIDDEN * HIDDEN, b_out, a_src, a_dst, hp_, N_NODES, 1);
    ln_out_kernel<<<N_NODES, HIDDEN>>>(ln_out_g, ln_out_b, batch, node_out);
    graph_out_kernel<<<(NUM_GRAPHS * HIDDEN + 255) / 256, 256>>>(out);
}